// round 12
// baseline (speedup 1.0000x reference)
#include <cuda_runtime.h>
#include <cstdint>
#include <math.h>

#define B_DIM 16384
#define I_DIM 1024
#define H_DIM 1024

// Arch-accelerated feature gate: tcgen05 body only when targeting sm_103a/sm_100a.
#if defined(__CUDA_ARCH__) && (defined(__CUDA_ARCH_FEAT_SM103_ALL) || defined(__CUDA_ARCH_FEAT_SM100_ALL))
#define HAVE_TCGEN05 1
#else
#define HAVE_TCGEN05 0
#endif

__device__ __forceinline__ uint32_t smem_u32(const void* p) {
    uint32_t a;
    asm("{ .reg .u64 t; cvta.to.shared.u64 t, %1; cvt.u32.u64 %0, t; }" : "=r"(a) : "l"(p));
    return a;
}

// ===========================================================================
// PATH A: tcgen05 cg2 tf32 — round-11 pipeline with ONE conceptual change:
// half-width N-tiles (N=64/pair, TMEM 256 cols, 28KB stages) so TWO
// cluster-pairs co-reside per SM-pair (2 CTAs/SM) and hide each other's
// sync/memory latency on the shared tensor pipe.
// ===========================================================================
#if HAVE_TCGEN05

#define MBAR_INIT(addr, cnt) \
    asm volatile("mbarrier.init.shared.b64 [%0], %1;" :: "r"(addr), "r"(cnt) : "memory")
#define MBAR_ARRIVE(addr) \
    asm volatile("mbarrier.arrive.shared.b64 _, [%0];" :: "r"(addr) : "memory")
#define MBAR_ARRIVE_RANK0(addr) \
    asm volatile("{\n\t.reg .b32 r;\n\t.reg .b32 z;\n\tmov.b32 z, 0;\n\t" \
                 "mapa.shared::cluster.u32 r, %0, z;\n\t" \
                 "mbarrier.arrive.shared::cluster.b64 _, [r];\n\t}" \
                 :: "r"(addr) : "memory")
#define MBAR_WAIT(addr, ph) do {                                                   \
    uint32_t _m = (addr); uint32_t _p = (ph); uint32_t _done;                      \
    asm volatile("{\n\t.reg .pred p;\n\t"                                          \
        "mbarrier.try_wait.parity.acquire.cta.shared::cta.b64 p, [%1], %2;\n\t"    \
        "selp.b32 %0, 1, 0, p;\n\t}"                                               \
        : "=r"(_done) : "r"(_m), "r"(_p) : "memory");                              \
    if (!_done) {                                                                  \
        asm volatile("{\n\t.reg .pred P1;\n\t"                                     \
            "WL_%=:\n\t"                                                           \
            "mbarrier.try_wait.parity.acquire.cta.shared::cta.b64 P1, [%0], %1, 0x989680;\n\t" \
            "@P1 bra.uni WD_%=;\n\t"                                               \
            "bra.uni WL_%=;\n\t"                                                   \
            "WD_%=:\n\t}"                                                          \
            :: "r"(_m), "r"(_p) : "memory");                                       \
    }                                                                              \
} while (0)

__device__ __forceinline__ void cp16(uint32_t dst, const float* src) {
    asm volatile("cp.async.cg.shared.global [%0], [%1], 16;" :: "r"(dst), "l"(src));
}

#define CPASYNC_ARRIVE(addr) \
    asm volatile("cp.async.mbarrier.arrive.noinc.shared::cta.b64 [%0];" :: "r"(addr) : "memory")

#define ALLOC_CG2(res, n) \
    asm volatile("tcgen05.alloc.cta_group::2.sync.aligned.shared::cta.b32 [%0], %1;" :: "r"(res), "r"(n) : "memory")
#define DEALLOC_CG2(t, n) \
    asm volatile("tcgen05.dealloc.cta_group::2.sync.aligned.b32 %0, %1;" :: "r"(t), "r"(n))
#define RELINQ_CG2() \
    asm volatile("tcgen05.relinquish_alloc_permit.cta_group::2.sync.aligned;")
#define COMMIT_MC(addr) \
    asm volatile("tcgen05.commit.cta_group::2.mbarrier::arrive::one.shared::cluster.multicast::cluster.b64 [%0], %1;" \
                 :: "r"(addr), "h"((uint16_t)3) : "memory")
#define TC_FENCE_BEFORE() asm volatile("tcgen05.fence::before_thread_sync;" ::: "memory")
#define TC_FENCE_AFTER()  asm volatile("tcgen05.fence::after_thread_sync;" ::: "memory")
#define TC_WAIT_LD()      asm volatile("tcgen05.wait::ld.sync.aligned;" ::: "memory")
#define CLUSTER_SYNC_() do { \
    asm volatile("barrier.cluster.arrive.aligned;" ::: "memory"); \
    asm volatile("barrier.cluster.wait.aligned;" ::: "memory"); } while (0)

#define LD_X16(r, a) \
    asm volatile("tcgen05.ld.sync.aligned.32x32b.x16.b32 " \
        "{%0, %1, %2, %3, %4, %5, %6, %7, %8, %9, %10, %11, %12, %13, %14, %15}, [%16];" \
        : "=r"((r)[0]), "=r"((r)[1]), "=r"((r)[2]), "=r"((r)[3]), \
          "=r"((r)[4]), "=r"((r)[5]), "=r"((r)[6]), "=r"((r)[7]), \
          "=r"((r)[8]), "=r"((r)[9]), "=r"((r)[10]), "=r"((r)[11]), \
          "=r"((r)[12]), "=r"((r)[13]), "=r"((r)[14]), "=r"((r)[15]) \
        : "r"(a))

__device__ __forceinline__ void mma_tf32_cg2(uint32_t d, uint64_t ad, uint64_t bd,
                                             uint32_t idesc, uint32_t en) {
    asm volatile(
        "{\n\t.reg .pred p;\n\tsetp.ne.u32 p, %4, 0;\n\t"
        "tcgen05.mma.cta_group::2.kind::tf32 [%0], %1, %2, %3, "
        "{%5, %5, %5, %5, %5, %5, %5, %5}, p;\n\t}"
        :: "r"(d), "l"(ad), "l"(bd), "r"(idesc), "r"(en), "r"(0u)
        : "memory");
}

__device__ __forceinline__ uint64_t sdesc(uint32_t addr) {
    return ((uint64_t)2 << 61) | ((uint64_t)1 << 46) | ((uint64_t)64 << 32) |
           ((uint64_t)1 << 16) | ((addr >> 4) & 0x3FFF);
}

#endif // HAVE_TCGEN05

constexpr int NST = 4;                 // physical 28KB stages (2 per super-buffer)
constexpr int STAGE_BYTES = 28672;     // A 16KB + 3x B 4KB (32 W-rows/gate/CTA)
constexpr int SMEM_STAGE0 = 2048;
constexpr int SMEM_TOTAL_TC = SMEM_STAGE0 + NST * STAGE_BYTES;   // 116736 (x2 = 228KB)

// idesc: dtype=f32(1)<<4, atype=tf32(2)<<7, btype=tf32(2)<<10, N/8<<17, M/16<<24
// N = 64 now.
constexpr uint32_t IDESC_TF32 = (1u << 4) | (2u << 7) | (2u << 10) | (8u << 17) | (16u << 24);

constexpr int TMEM_COLS = 256;   // 4 accumulators x 64 cols
constexpr int OFF_TMEM  = 0;
constexpr int OFF_FULL  = 16;    // 2 x 8B (per super-buffer)
constexpr int OFF_EMPTY = 48;    // 2 x 8B
constexpr int OFF_PAIR  = 80;    // 2 x 8B
constexpr int OFF_DONE  = 112;
constexpr int OFF_BIAS  = 128;   // 256 floats (4 x 64)

// De-bias for double RZ tf32 truncation (both operands raw).
#define TRUNC_DEBIAS 1.000677f

__global__ void __launch_bounds__(288, 2) __cluster_dims__(2, 1, 1)
gru_tc_kernel(const float* __restrict__ x, const float* __restrict__ h_prev,
              const float* __restrict__ Wiz, const float* __restrict__ Wir,
              const float* __restrict__ Wih, const float* __restrict__ Whz,
              const float* __restrict__ Whr, const float* __restrict__ Whh,
              const float* __restrict__ biz, const float* __restrict__ bir,
              const float* __restrict__ big, const float* __restrict__ bhz,
              const float* __restrict__ bhr, const float* __restrict__ bhh,
              float* __restrict__ out)
{
#if HAVE_TCGEN05
    extern __shared__ char smem[];
    const uint32_t sb = smem_u32(smem);
    const int tid = threadIdx.x;
    const uint32_t rank = blockIdx.x & 1;
    // N-fast pair raster: 16 N-tiles of 64 cols
    const int pair = blockIdx.x >> 1;
    const int colBase  = (pair & 15) * 64;
    const int rowBase  = (pair >> 4) * 256 + (int)rank * 128;
    const int wColBase = colBase + (int)rank * 32;   // this CTA's 32 W-rows/gate

    if (tid == 0) {
        for (int b = 0; b < 2; b++) {
            MBAR_INIT(sb + OFF_FULL  + b * 8, 256);
            MBAR_INIT(sb + OFF_EMPTY + b * 8, 1);
            MBAR_INIT(sb + OFF_PAIR  + b * 8, 2);
        }
        MBAR_INIT(sb + OFF_DONE, 1);
    }
    if (tid >= 256) {
        ALLOC_CG2(sb + OFF_TMEM, TMEM_COLS);
    }
    if (tid < 64) {
        int c = colBase + tid;
        float* bb = (float*)(smem + OFF_BIAS);
        bb[tid]       = biz[c] + bhz[c];
        bb[64 + tid]  = bir[c] + bhr[c];
        bb[128 + tid] = big[c];
        bb[192 + tid] = bhh[c];
    }
    __syncthreads();
    uint32_t tmem;
    asm volatile("ld.shared.b32 %0, [%1];" : "=r"(tmem) : "r"(sb + OFF_TMEM));
    CLUSTER_SYNC_();

    if (tid < 256) {
        // producers: per super-chunk fill 2 stages (14 cp.async/thread), 1 arrive
        const float* WI[3] = {Wiz, Wir, Wih};
        const float* WH[3] = {Whz, Whr, Whh};
#pragma unroll 1
        for (int s = 0; s < 32; s++) {
            const int b   = s & 1;
            const int pph = 1 ^ ((s >> 1) & 1);
            MBAR_WAIT(sb + OFF_EMPTY + b * 8, pph);
#pragma unroll
            for (int sub = 0; sub < 2; sub++) {
                const int chunk = 2 * s + sub;
                const float* Ap = (chunk < 32) ? x : h_prev;
                const int k0 = (chunk & 31) * 32;
                const uint32_t stb = sb + SMEM_STAGE0 + (2 * b + sub) * STAGE_BYTES;
                // A tile: 128 rows x 128B (4 x 16B per thread)
#pragma unroll
                for (int t = 0; t < 4; t++) {
                    int i = tid + t * 256;
                    int row = i >> 3, c16 = i & 7;
                    uint32_t off = (uint32_t)(row * 128 + c16 * 16);
                    cp16(stb + (off ^ ((off >> 3) & 0x70)),
                         Ap + (size_t)(rowBase + row) * I_DIM + k0 + c16 * 4);
                }
                // W tiles: 3 gates x 32 rows x 128B (3 x 16B per thread)
#pragma unroll
                for (int t = 0; t < 3; t++) {
                    int i = tid + t * 256;
                    int gate = i >> 8, w = i & 255;
                    int row = w >> 3, c16 = w & 7;
                    const float* W = (chunk < 32) ? WI[gate] : WH[gate];
                    uint32_t off = (uint32_t)(row * 128 + c16 * 16);
                    cp16(stb + 16384 + gate * 4096 + (off ^ ((off >> 3) & 0x70)),
                         W + (size_t)(wColBase + row) * I_DIM + k0 + c16 * 4);
                }
            }
            CPASYNC_ARRIVE(sb + OFF_FULL + b * 8);   // covers BOTH stages' loads
        }
    } else {
        // control: warp 8 — one sync round per super-chunk (24 dispatches)
        const int lane = tid - 256;
#pragma unroll 1
        for (int s = 0; s < 32; s++) {
            const int b  = s & 1;
            const int ph = (s >> 1) & 1;
            MBAR_WAIT(sb + OFF_FULL + b * 8, ph);        // both stages loaded
            if (rank == 0) {
                if (lane == 0) MBAR_ARRIVE(sb + OFF_PAIR + b * 8);
                MBAR_WAIT(sb + OFF_PAIR + b * 8, ph);    // both CTAs full
                if (lane == 0) {
#pragma unroll
                    for (int sub = 0; sub < 2; sub++) {
                        const int chunk = 2 * s + sub;
                        const uint32_t stb = sb + SMEM_STAGE0 + (2 * b + sub) * STAGE_BYTES;
                        const uint64_t aD = sdesc(stb);
                        const uint32_t tG = (chunk < 32) ? (tmem + 128) : (tmem + 192);
#pragma unroll
                        for (int g = 0; g < 3; g++) {
                            const uint64_t bD = sdesc(stb + 16384 + g * 4096);
                            const uint32_t dcol = (g == 0) ? tmem : ((g == 1) ? (tmem + 64) : tG);
#pragma unroll
                            for (int ks = 0; ks < 4; ks++) {
                                uint32_t en = !(ks == 0 && (chunk == 0 || (chunk == 32 && g == 2)));
                                mma_tf32_cg2(dcol, aD + ks * 2, bD + ks * 2, IDESC_TF32, en);
                            }
                        }
                    }
                    COMMIT_MC(sb + OFF_EMPTY + b * 8);   // frees super-buffer in BOTH CTAs
                }
            } else {
                if (lane == 0) MBAR_ARRIVE_RANK0(sb + OFF_PAIR + b * 8);
            }
        }
        if (rank == 0 && lane == 0) COMMIT_MC(sb + OFF_DONE);
    }

    // epilogue: warps 0-3 read TMEM (4 acc x 64 cols), de-bias, fuse activations
    if (tid < 128) {
        MBAR_WAIT(sb + OFF_DONE, 0);
        TC_FENCE_AFTER();
        const int warp = tid >> 5, lane = tid & 31;
        const int grow = rowBase + warp * 32 + lane;
        const float* hrow = h_prev + (size_t)grow * H_DIM + colBase;
        float* orow = out + (size_t)grow * H_DIM + colBase;
        const float* bb = (const float*)(smem + OFF_BIAS);
#pragma unroll 1
        for (int c0 = 0; c0 < 64; c0 += 16) {
            uint32_t rz[16], rr[16], rg[16], rh[16];
            LD_X16(rz, tmem + c0);
            LD_X16(rr, tmem + 64 + c0);
            LD_X16(rg, tmem + 128 + c0);
            LD_X16(rh, tmem + 192 + c0);
            TC_WAIT_LD();
            TC_FENCE_BEFORE();
            float o[16];
#pragma unroll
            for (int j = 0; j < 16; j++) {
                const int cc = c0 + j;
                float az = __uint_as_float(rz[j]) * TRUNC_DEBIAS;
                float ar = __uint_as_float(rr[j]) * TRUNC_DEBIAS;
                float ag = __uint_as_float(rg[j]) * TRUNC_DEBIAS;
                float ah = __uint_as_float(rh[j]) * TRUNC_DEBIAS;
                float z = 1.f / (1.f + __expf(-(az + bb[cc])));
                float r = 1.f / (1.f + __expf(-(ar + bb[64 + cc])));
                float g = tanhf(ag + bb[128 + cc] + r * (ah + bb[192 + cc]));
                o[j] = (1.f - z) * g + z * hrow[cc];
            }
#pragma unroll
            for (int q = 0; q < 4; q++)
                *reinterpret_cast<float4*>(orow + c0 + q * 4) =
                    make_float4(o[q * 4], o[q * 4 + 1], o[q * 4 + 2], o[q * 4 + 3]);
        }
    }

    __syncthreads();
    if (tid >= 256) {
        RELINQ_CG2();
        DEALLOC_CG2(tmem, TMEM_COLS);
    }
    CLUSTER_SYNC_();
#endif // HAVE_TCGEN05
}

// ===========================================================================
// PATH B: mma.sync tf32 fallback (baseline-sm_103 cubin only; hedge).
// ===========================================================================
constexpr int BM = 128;
constexpr int BN = 64;
constexpr int LDS_STRIDE = 36;
constexpr int A_FLOATS = BM * LDS_STRIDE;
constexpr int B_FLOATS = BN * LDS_STRIDE;
constexpr int STAGE_FLOATS = A_FLOATS + 3 * B_FLOATS;
constexpr int SMEM_BYTES_MMA = 2 * STAGE_FLOATS * 4;

#if !HAVE_TCGEN05

__device__ __forceinline__ void cp_async16f(float* dst, const float* src) {
    unsigned d = (unsigned)__cvta_generic_to_shared(dst);
    asm volatile("cp.async.cg.shared.global [%0], [%1], 16;" :: "r"(d), "l"(src));
}

__device__ __forceinline__ void mma_tf32_sync(float d[4], const unsigned a[4], unsigned b0, unsigned b1) {
    asm volatile(
        "mma.sync.aligned.m16n8k8.row.col.f32.tf32.tf32.f32 "
        "{%0,%1,%2,%3}, {%4,%5,%6,%7}, {%8,%9}, {%0,%1,%2,%3};"
        : "+f"(d[0]), "+f"(d[1]), "+f"(d[2]), "+f"(d[3])
        : "r"(a[0]), "r"(a[1]), "r"(a[2]), "r"(a[3]), "r"(b0), "r"(b1));
}

__device__ __forceinline__ void compute_step_mma(
    const float* st, int wm, int wn, int gq, int tg,
    float (&accZ)[2][4][4], float (&accR)[2][4][4], float (&accT)[2][4][4])
{
#pragma unroll
    for (int kk = 0; kk < 4; kk++) {
        unsigned a[2][4];
        const int kbase = kk * 8 + tg;
#pragma unroll
        for (int mt = 0; mt < 2; mt++) {
            const int rb = wm * 32 + mt * 16;
            a[mt][0] = __float_as_uint(st[(rb + gq    ) * LDS_STRIDE + kbase    ]);
            a[mt][1] = __float_as_uint(st[(rb + gq + 8) * LDS_STRIDE + kbase    ]);
            a[mt][2] = __float_as_uint(st[(rb + gq    ) * LDS_STRIDE + kbase + 4]);
            a[mt][3] = __float_as_uint(st[(rb + gq + 8) * LDS_STRIDE + kbase + 4]);
        }
#pragma unroll
        for (int gt = 0; gt < 3; gt++) {
            const float* Bs = st + A_FLOATS + gt * B_FLOATS;
            float (&acc)[2][4][4] = (gt == 0) ? accZ : ((gt == 1) ? accR : accT);
#pragma unroll
            for (int nt = 0; nt < 4; nt++) {
                const int cb = wn * 32 + nt * 8 + gq;
                unsigned b0 = __float_as_uint(Bs[cb * LDS_STRIDE + kbase    ]);
                unsigned b1 = __float_as_uint(Bs[cb * LDS_STRIDE + kbase + 4]);
#pragma unroll
                for (int mt = 0; mt < 2; mt++)
                    mma_tf32_sync(acc[mt][nt], a[mt], b0, b1);
            }
        }
    }
}
#endif // !HAVE_TCGEN05

__global__ void __launch_bounds__(256, 1) gru_mma_kernel(
    const float* __restrict__ x, const float* __restrict__ h_prev,
    const float* __restrict__ Wiz, const float* __restrict__ Wir,
    const float* __restrict__ Wih, const float* __restrict__ Whz,
    const float* __restrict__ Whr, const float* __restrict__ Whh,
    const float* __restrict__ biz, const float* __restrict__ bir,
    const float* __restrict__ big, const float* __restrict__ bhz,
    const float* __restrict__ bhr, const float* __restrict__ bhh,
    float* __restrict__ out)
{
#if !HAVE_TCGEN05
    extern __shared__ float smemf[];
    const int tid = threadIdx.x;
    const int lane = tid & 31;
    const int warp = tid >> 5;
    const int wm = warp >> 1;
    const int wn = warp & 1;
    const int gq = lane >> 2;
    const int tg = lane & 3;

    const int rowBase = blockIdx.y * BM;
    const int colBase = blockIdx.x * BN;
    const float* WI[3] = {Wiz, Wir, Wih};
    const float* WH[3] = {Whz, Whr, Whh};

    float accZ[2][4][4], accR[2][4][4], accG[2][4][4], accH[2][4][4];
#pragma unroll
    for (int mt = 0; mt < 2; mt++)
#pragma unroll
        for (int nt = 0; nt < 4; nt++)
#pragma unroll
            for (int r = 0; r < 4; r++) {
                accZ[mt][nt][r] = 0.f; accR[mt][nt][r] = 0.f;
                accG[mt][nt][r] = 0.f; accH[mt][nt][r] = 0.f;
            }

#define ISSUE_LOAD_MMA(s)                                                          \
    do {                                                                           \
        const float* Aptr = ((s) < 32) ? x : h_prev;                               \
        const int k0 = ((s) & 31) * 32;                                            \
        float* st = smemf + ((s) & 1) * STAGE_FLOATS;                              \
        _Pragma("unroll")                                                          \
        for (int i = 0; i < 4; i++) {                                              \
            int lin = tid + i * 256;                                               \
            int r = lin >> 3, c4 = lin & 7;                                        \
            cp_async16f(st + r * LDS_STRIDE + c4 * 4,                              \
                        Aptr + (size_t)(rowBase + r) * I_DIM + k0 + c4 * 4);       \
        }                                                                          \
        _Pragma("unroll")                                                          \
        for (int gt = 0; gt < 3; gt++) {                                           \
            const float* W = ((s) < 32) ? WI[gt] : WH[gt];                         \
            float* bs = st + A_FLOATS + gt * B_FLOATS;                             \
            _Pragma("unroll")                                                      \
            for (int i = 0; i < 2; i++) {                                          \
                int lin = tid + i * 256;                                           \
                int r = lin >> 3, c4 = lin & 7;                                    \
                cp_async16f(bs + r * LDS_STRIDE + c4 * 4,                          \
                            W + (size_t)(colBase + r) * I_DIM + k0 + c4 * 4);      \
            }                                                                      \
        }                                                                          \
        asm volatile("cp.async.commit_group;");                                    \
    } while (0)

    ISSUE_LOAD_MMA(0);

#pragma unroll 1
    for (int s = 0; s < 64; s++) {
        if (s + 1 < 64) {
            ISSUE_LOAD_MMA(s + 1);
            asm volatile("cp.async.wait_group 1;");
        } else {
            asm volatile("cp.async.wait_group 0;");
        }
        __syncthreads();
        const float* st = smemf + (s & 1) * STAGE_FLOATS;
        if (s < 32) compute_step_mma(st, wm, wn, gq, tg, accZ, accR, accG);
        else        compute_step_mma(st, wm, wn, gq, tg, accZ, accR, accH);
        __syncthreads();
    }
#undef ISSUE_LOAD_MMA

    const int colW = colBase + wn * 32;
#pragma unroll
    for (int mt = 0; mt < 2; mt++) {
#pragma unroll
        for (int mh = 0; mh < 2; mh++) {
            const int row = rowBase + wm * 32 + mt * 16 + gq + mh * 8;
            const float* hrow = h_prev + (size_t)row * H_DIM;
            float* orow = out + (size_t)row * H_DIM;
#pragma unroll
            for (int nt = 0; nt < 4; nt++) {
                const int c = colW + nt * 8 + tg * 2;
                float h2[2];
#pragma unroll
                for (int j = 0; j < 2; j++) {
                    const int col = c + j;
                    const int ridx = mh * 2 + j;
                    float zp = accZ[mt][nt][ridx] + biz[col] + bhz[col];
                    float rp = accR[mt][nt][ridx] + bir[col] + bhr[col];
                    float z = 1.f / (1.f + __expf(-zp));
                    float r = 1.f / (1.f + __expf(-rp));
                    float gp = accG[mt][nt][ridx] + big[col] + r * (accH[mt][nt][ridx] + bhh[col]);
                    float g = tanhf(gp);
                    h2[j] = (1.f - z) * g + z * hrow[col];
                }
                *reinterpret_cast<float2*>(orow + c) = make_float2(h2[0], h2[1]);
            }
        }
    }
#endif // !HAVE_TCGEN05
}

// ---------------------------------------------------------------------------
// Launch: main GEMM first, hedge second.
// ---------------------------------------------------------------------------
extern "C" void kernel_launch(void* const* d_in, const int* in_sizes, int n_in,
                              void* d_out, int out_size)
{
    const float* x   = (const float*)d_in[0];
    const float* h   = (const float*)d_in[1];
    const float* Wiz = (const float*)d_in[2];
    const float* biz = (const float*)d_in[3];
    const float* Wir = (const float*)d_in[4];
    const float* bir = (const float*)d_in[5];
    const float* Wih = (const float*)d_in[6];
    const float* big = (const float*)d_in[7];
    const float* Whz = (const float*)d_in[8];
    const float* bhz = (const float*)d_in[9];
    const float* Whr = (const float*)d_in[10];
    const float* bhr = (const float*)d_in[11];
    const float* Whh = (const float*)d_in[12];
    const float* bhh = (const float*)d_in[13];
    float* out = (float*)d_out;

    // 1) Path A: tcgen05 main kernel — 2048 CTAs (1024 pairs), 2 CTAs/SM
    cudaFuncSetAttribute(gru_tc_kernel, cudaFuncAttributeMaxDynamicSharedMemorySize, SMEM_TOTAL_TC);
    {
        dim3 grid(2048, 1);
        gru_tc_kernel<<<grid, 288, SMEM_TOTAL_TC>>>(
            x, h, Wiz, Wir, Wih, Whz, Whr, Whh,
            biz, bir, big, bhz, bhr, bhh, out);
    }

    // 2) Path B hedge (empty cubin on sm_103a)
    cudaFuncSetAttribute(gru_mma_kernel, cudaFuncAttributeMaxDynamicSharedMemorySize, SMEM_BYTES_MMA);
    {
        dim3 grid(H_DIM / BN, B_DIM / BM);
        gru_mma_kernel<<<grid, 256, SMEM_BYTES_MMA>>>(
            x, h, Wiz, Wir, Wih, Whz, Whr, Whh,
            biz, bir, big, bhz, bhr, bhh, out);
    }
}

// round 13
// speedup vs baseline: 1.4196x; 1.4196x over previous
#include <cuda_runtime.h>
#include <cstdint>
#include <math.h>

#define B_DIM 16384
#define I_DIM 1024
#define H_DIM 1024

// Arch-accelerated feature gate: tcgen05 body only when targeting sm_103a/sm_100a.
#if defined(__CUDA_ARCH__) && (defined(__CUDA_ARCH_FEAT_SM103_ALL) || defined(__CUDA_ARCH_FEAT_SM100_ALL))
#define HAVE_TCGEN05 1
#else
#define HAVE_TCGEN05 0
#endif

__device__ __forceinline__ uint32_t smem_u32(const void* p) {
    uint32_t a;
    asm("{ .reg .u64 t; cvta.to.shared.u64 t, %1; cvt.u32.u64 %0, t; }" : "=r"(a) : "l"(p));
    return a;
}

// ===========================================================================
// PATH A: tcgen05 cg2 tf32 — round-11 config (N=128, NST=4, 2 super-buffers,
// N-fast raster, raw operands + de-bias) with ONE change: FULL/PAIR barriers
// are per physical stage, so MMAs for a super-chunk's first stage issue after
// only 40KB of its 80KB fill (earlier tensor-pipe start, smaller fill gap).
// EMPTY/commit stay per super-buffer (cheap recycling, 32 commits).
// ===========================================================================
#if HAVE_TCGEN05

#define MBAR_INIT(addr, cnt) \
    asm volatile("mbarrier.init.shared.b64 [%0], %1;" :: "r"(addr), "r"(cnt) : "memory")
#define MBAR_ARRIVE(addr) \
    asm volatile("mbarrier.arrive.shared.b64 _, [%0];" :: "r"(addr) : "memory")
#define MBAR_ARRIVE_RANK0(addr) \
    asm volatile("{\n\t.reg .b32 r;\n\t.reg .b32 z;\n\tmov.b32 z, 0;\n\t" \
                 "mapa.shared::cluster.u32 r, %0, z;\n\t" \
                 "mbarrier.arrive.shared::cluster.b64 _, [r];\n\t}" \
                 :: "r"(addr) : "memory")
#define MBAR_WAIT(addr, ph) do {                                                   \
    uint32_t _m = (addr); uint32_t _p = (ph); uint32_t _done;                      \
    asm volatile("{\n\t.reg .pred p;\n\t"                                          \
        "mbarrier.try_wait.parity.acquire.cta.shared::cta.b64 p, [%1], %2;\n\t"    \
        "selp.b32 %0, 1, 0, p;\n\t}"                                               \
        : "=r"(_done) : "r"(_m), "r"(_p) : "memory");                              \
    if (!_done) {                                                                  \
        asm volatile("{\n\t.reg .pred P1;\n\t"                                     \
            "WL_%=:\n\t"                                                           \
            "mbarrier.try_wait.parity.acquire.cta.shared::cta.b64 P1, [%0], %1, 0x989680;\n\t" \
            "@P1 bra.uni WD_%=;\n\t"                                               \
            "bra.uni WL_%=;\n\t"                                                   \
            "WD_%=:\n\t}"                                                          \
            :: "r"(_m), "r"(_p) : "memory");                                       \
    }                                                                              \
} while (0)

__device__ __forceinline__ void cp16(uint32_t dst, const float* src) {
    asm volatile("cp.async.cg.shared.global [%0], [%1], 16;" :: "r"(dst), "l"(src));
}

#define CPASYNC_ARRIVE(addr) \
    asm volatile("cp.async.mbarrier.arrive.noinc.shared::cta.b64 [%0];" :: "r"(addr) : "memory")

#define ALLOC_CG2(res, n) \
    asm volatile("tcgen05.alloc.cta_group::2.sync.aligned.shared::cta.b32 [%0], %1;" :: "r"(res), "r"(n) : "memory")
#define DEALLOC_CG2(t, n) \
    asm volatile("tcgen05.dealloc.cta_group::2.sync.aligned.b32 %0, %1;" :: "r"(t), "r"(n))
#define RELINQ_CG2() \
    asm volatile("tcgen05.relinquish_alloc_permit.cta_group::2.sync.aligned;")
#define COMMIT_MC(addr) \
    asm volatile("tcgen05.commit.cta_group::2.mbarrier::arrive::one.shared::cluster.multicast::cluster.b64 [%0], %1;" \
                 :: "r"(addr), "h"((uint16_t)3) : "memory")
#define TC_FENCE_BEFORE() asm volatile("tcgen05.fence::before_thread_sync;" ::: "memory")
#define TC_FENCE_AFTER()  asm volatile("tcgen05.fence::after_thread_sync;" ::: "memory")
#define TC_WAIT_LD()      asm volatile("tcgen05.wait::ld.sync.aligned;" ::: "memory")
#define CLUSTER_SYNC_() do { \
    asm volatile("barrier.cluster.arrive.aligned;" ::: "memory"); \
    asm volatile("barrier.cluster.wait.aligned;" ::: "memory"); } while (0)

#define LD_X16(r, a) \
    asm volatile("tcgen05.ld.sync.aligned.32x32b.x16.b32 " \
        "{%0, %1, %2, %3, %4, %5, %6, %7, %8, %9, %10, %11, %12, %13, %14, %15}, [%16];" \
        : "=r"((r)[0]), "=r"((r)[1]), "=r"((r)[2]), "=r"((r)[3]), \
          "=r"((r)[4]), "=r"((r)[5]), "=r"((r)[6]), "=r"((r)[7]), \
          "=r"((r)[8]), "=r"((r)[9]), "=r"((r)[10]), "=r"((r)[11]), \
          "=r"((r)[12]), "=r"((r)[13]), "=r"((r)[14]), "=r"((r)[15]) \
        : "r"(a))

__device__ __forceinline__ void mma_tf32_cg2(uint32_t d, uint64_t ad, uint64_t bd,
                                             uint32_t idesc, uint32_t en) {
    asm volatile(
        "{\n\t.reg .pred p;\n\tsetp.ne.u32 p, %4, 0;\n\t"
        "tcgen05.mma.cta_group::2.kind::tf32 [%0], %1, %2, %3, "
        "{%5, %5, %5, %5, %5, %5, %5, %5}, p;\n\t}"
        :: "r"(d), "l"(ad), "l"(bd), "r"(idesc), "r"(en), "r"(0u)
        : "memory");
}

__device__ __forceinline__ uint64_t sdesc(uint32_t addr) {
    return ((uint64_t)2 << 61) | ((uint64_t)1 << 46) | ((uint64_t)64 << 32) |
           ((uint64_t)1 << 16) | ((addr >> 4) & 0x3FFF);
}

#endif // HAVE_TCGEN05

constexpr int NST = 4;                 // physical 40KB stages (2 per super-buffer)
constexpr int STAGE_BYTES = 40960;     // A 16KB + 3x B 8KB
constexpr int SMEM_STAGE0 = 4096;
constexpr int SMEM_TOTAL_TC = SMEM_STAGE0 + NST * STAGE_BYTES;   // 167936

// idesc: dtype=f32(1)<<4, atype=tf32(2)<<7, btype=tf32(2)<<10, N/8<<17, M/16<<24
constexpr uint32_t IDESC_TF32 = (1u << 4) | (2u << 7) | (2u << 10) | (16u << 17) | (16u << 24);

constexpr int OFF_TMEM  = 0;
constexpr int OFF_FULL  = 16;    // 4 x 8B  (per physical stage)
constexpr int OFF_EMPTY = 48;    // 2 x 8B  (per super-buffer)
constexpr int OFF_PAIR  = 64;    // 4 x 8B  (per physical stage)
constexpr int OFF_DONE  = 96;
constexpr int OFF_BIAS  = 128;   // 512 floats

// De-bias for double RZ tf32 truncation (both operands raw).
#define TRUNC_DEBIAS 1.000677f

__global__ void __launch_bounds__(288, 1) __cluster_dims__(2, 1, 1)
gru_tc_kernel(const float* __restrict__ x, const float* __restrict__ h_prev,
              const float* __restrict__ Wiz, const float* __restrict__ Wir,
              const float* __restrict__ Wih, const float* __restrict__ Whz,
              const float* __restrict__ Whr, const float* __restrict__ Whh,
              const float* __restrict__ biz, const float* __restrict__ bir,
              const float* __restrict__ big, const float* __restrict__ bhz,
              const float* __restrict__ bhr, const float* __restrict__ bhh,
              float* __restrict__ out)
{
#if HAVE_TCGEN05
    extern __shared__ char smem[];
    const uint32_t sb = smem_u32(smem);
    const int tid = threadIdx.x;
    const uint32_t rank = blockIdx.x & 1;
    // N-fast pair raster (proven round 10/11)
    const int pair = blockIdx.x >> 1;
    const int colBase  = (pair & 7) * 128;
    const int rowBase  = (pair >> 3) * 256 + (int)rank * 128;
    const int wColBase = colBase + (int)rank * 64;

    if (tid == 0) {
        for (int st = 0; st < NST; st++) {
            MBAR_INIT(sb + OFF_FULL + st * 8, 256);
            MBAR_INIT(sb + OFF_PAIR + st * 8, 2);
        }
        for (int b = 0; b < 2; b++)
            MBAR_INIT(sb + OFF_EMPTY + b * 8, 1);
        MBAR_INIT(sb + OFF_DONE, 1);
    }
    if (tid >= 256) {
        ALLOC_CG2(sb + OFF_TMEM, 512);
    }
    if (tid < 128) {
        int c = colBase + tid;
        float* bb = (float*)(smem + OFF_BIAS);
        bb[tid]       = biz[c] + bhz[c];
        bb[128 + tid] = bir[c] + bhr[c];
        bb[256 + tid] = big[c];
        bb[384 + tid] = bhh[c];
    }
    __syncthreads();
    uint32_t tmem;
    asm volatile("ld.shared.b32 %0, [%1];" : "=r"(tmem) : "r"(sb + OFF_TMEM));
    CLUSTER_SYNC_();

    if (tid < 256) {
        // producers: per super-chunk: 1 EMPTY wait, fill stage 2b then 2b+1,
        // arriving the per-stage FULL after each 40KB stage.
        const float* WI[3] = {Wiz, Wir, Wih};
        const float* WH[3] = {Whz, Whr, Whh};
#pragma unroll 1
        for (int s = 0; s < 32; s++) {
            const int b   = s & 1;
            const int pph = 1 ^ ((s >> 1) & 1);
            MBAR_WAIT(sb + OFF_EMPTY + b * 8, pph);
#pragma unroll
            for (int sub = 0; sub < 2; sub++) {
                const int chunk = 2 * s + sub;
                const int st = 2 * b + sub;
                const float* Ap = (chunk < 32) ? x : h_prev;
                const int k0 = (chunk & 31) * 32;
                const uint32_t stb = sb + SMEM_STAGE0 + st * STAGE_BYTES;
#pragma unroll
                for (int t = 0; t < 4; t++) {
                    int i = tid + t * 256;
                    int row = i >> 3, c16 = i & 7;
                    uint32_t off = (uint32_t)(row * 128 + c16 * 16);
                    cp16(stb + (off ^ ((off >> 3) & 0x70)),
                         Ap + (size_t)(rowBase + row) * I_DIM + k0 + c16 * 4);
                }
#pragma unroll
                for (int t = 0; t < 6; t++) {
                    const int gate = t >> 1;
                    const float* W = (chunk < 32) ? WI[gate] : WH[gate];
                    int i = (t & 1) * 256 + tid;
                    int row = i >> 3, c16 = i & 7;
                    uint32_t off = (uint32_t)(row * 128 + c16 * 16);
                    cp16(stb + 16384 + gate * 8192 + (off ^ ((off >> 3) & 0x70)),
                         W + (size_t)(wColBase + row) * I_DIM + k0 + c16 * 4);
                }
                CPASYNC_ARRIVE(sb + OFF_FULL + st * 8);   // per-stage completion
            }
        }
    } else {
        // control: warp 8 — per stage FULL/PAIR, per super-buffer commit
        const int lane = tid - 256;
#pragma unroll 1
        for (int s = 0; s < 32; s++) {
            const int b  = s & 1;
            const int ph = (s >> 1) & 1;
#pragma unroll
            for (int sub = 0; sub < 2; sub++) {
                const int st = 2 * b + sub;
                const int chunk = 2 * s + sub;
                MBAR_WAIT(sb + OFF_FULL + st * 8, ph);       // this stage loaded
                if (rank == 0) {
                    if (lane == 0) MBAR_ARRIVE(sb + OFF_PAIR + st * 8);
                    MBAR_WAIT(sb + OFF_PAIR + st * 8, ph);   // both CTAs' stage full
                    if (lane == 0) {
                        const uint32_t stb = sb + SMEM_STAGE0 + st * STAGE_BYTES;
                        const uint64_t aD = sdesc(stb);
                        const uint32_t tG = (chunk < 32) ? (tmem + 256) : (tmem + 384);
#pragma unroll
                        for (int g = 0; g < 3; g++) {
                            const uint64_t bD = sdesc(stb + 16384 + g * 8192);
                            const uint32_t dcol = (g == 0) ? tmem : ((g == 1) ? (tmem + 128) : tG);
#pragma unroll
                            for (int ks = 0; ks < 4; ks++) {
                                uint32_t en = !(ks == 0 && (chunk == 0 || (chunk == 32 && g == 2)));
                                mma_tf32_cg2(dcol, aD + ks * 2, bD + ks * 2, IDESC_TF32, en);
                            }
                        }
                    }
                } else {
                    if (lane == 0) MBAR_ARRIVE_RANK0(sb + OFF_PAIR + st * 8);
                }
            }
            if (rank == 0 && lane == 0)
                COMMIT_MC(sb + OFF_EMPTY + b * 8);   // frees super-buffer in BOTH CTAs
        }
        if (rank == 0 && lane == 0) COMMIT_MC(sb + OFF_DONE);
    }

    // epilogue: warps 0-3 read TMEM, de-bias, fuse activations
    if (tid < 128) {
        MBAR_WAIT(sb + OFF_DONE, 0);
        TC_FENCE_AFTER();
        const int warp = tid >> 5, lane = tid & 31;
        const int grow = rowBase + warp * 32 + lane;
        const float* hrow = h_prev + (size_t)grow * H_DIM + colBase;
        float* orow = out + (size_t)grow * H_DIM + colBase;
        const float* bb = (const float*)(smem + OFF_BIAS);
#pragma unroll 1
        for (int c0 = 0; c0 < 128; c0 += 16) {
            uint32_t rz[16], rr[16], rg[16], rh[16];
            LD_X16(rz, tmem + c0);
            LD_X16(rr, tmem + 128 + c0);
            LD_X16(rg, tmem + 256 + c0);
            LD_X16(rh, tmem + 384 + c0);
            TC_WAIT_LD();
            TC_FENCE_BEFORE();
            float o[16];
#pragma unroll
            for (int j = 0; j < 16; j++) {
                const int cc = c0 + j;
                float az = __uint_as_float(rz[j]) * TRUNC_DEBIAS;
                float ar = __uint_as_float(rr[j]) * TRUNC_DEBIAS;
                float ag = __uint_as_float(rg[j]) * TRUNC_DEBIAS;
                float ah = __uint_as_float(rh[j]) * TRUNC_DEBIAS;
                float z = 1.f / (1.f + __expf(-(az + bb[cc])));
                float r = 1.f / (1.f + __expf(-(ar + bb[128 + cc])));
                float g = tanhf(ag + bb[256 + cc] + r * (ah + bb[384 + cc]));
                o[j] = (1.f - z) * g + z * hrow[cc];
            }
#pragma unroll
            for (int q = 0; q < 4; q++)
                *reinterpret_cast<float4*>(orow + c0 + q * 4) =
                    make_float4(o[q * 4], o[q * 4 + 1], o[q * 4 + 2], o[q * 4 + 3]);
        }
    }

    __syncthreads();
    if (tid >= 256) {
        RELINQ_CG2();
        DEALLOC_CG2(tmem, 512);
    }
    CLUSTER_SYNC_();
#endif // HAVE_TCGEN05
}

// ===========================================================================
// PATH B: mma.sync tf32 fallback (baseline-sm_103 cubin only; hedge).
// ===========================================================================
constexpr int BM = 128;
constexpr int BN = 64;
constexpr int LDS_STRIDE = 36;
constexpr int A_FLOATS = BM * LDS_STRIDE;
constexpr int B_FLOATS = BN * LDS_STRIDE;
constexpr int STAGE_FLOATS = A_FLOATS + 3 * B_FLOATS;
constexpr int SMEM_BYTES_MMA = 2 * STAGE_FLOATS * 4;

#if !HAVE_TCGEN05

__device__ __forceinline__ void cp_async16f(float* dst, const float* src) {
    unsigned d = (unsigned)__cvta_generic_to_shared(dst);
    asm volatile("cp.async.cg.shared.global [%0], [%1], 16;" :: "r"(d), "l"(src));
}

__device__ __forceinline__ void mma_tf32_sync(float d[4], const unsigned a[4], unsigned b0, unsigned b1) {
    asm volatile(
        "mma.sync.aligned.m16n8k8.row.col.f32.tf32.tf32.f32 "
        "{%0,%1,%2,%3}, {%4,%5,%6,%7}, {%8,%9}, {%0,%1,%2,%3};"
        : "+f"(d[0]), "+f"(d[1]), "+f"(d[2]), "+f"(d[3])
        : "r"(a[0]), "r"(a[1]), "r"(a[2]), "r"(a[3]), "r"(b0), "r"(b1));
}

__device__ __forceinline__ void compute_step_mma(
    const float* st, int wm, int wn, int gq, int tg,
    float (&accZ)[2][4][4], float (&accR)[2][4][4], float (&accT)[2][4][4])
{
#pragma unroll
    for (int kk = 0; kk < 4; kk++) {
        unsigned a[2][4];
        const int kbase = kk * 8 + tg;
#pragma unroll
        for (int mt = 0; mt < 2; mt++) {
            const int rb = wm * 32 + mt * 16;
            a[mt][0] = __float_as_uint(st[(rb + gq    ) * LDS_STRIDE + kbase    ]);
            a[mt][1] = __float_as_uint(st[(rb + gq + 8) * LDS_STRIDE + kbase    ]);
            a[mt][2] = __float_as_uint(st[(rb + gq    ) * LDS_STRIDE + kbase + 4]);
            a[mt][3] = __float_as_uint(st[(rb + gq + 8) * LDS_STRIDE + kbase + 4]);
        }
#pragma unroll
        for (int gt = 0; gt < 3; gt++) {
            const float* Bs = st + A_FLOATS + gt * B_FLOATS;
            float (&acc)[2][4][4] = (gt == 0) ? accZ : ((gt == 1) ? accR : accT);
#pragma unroll
            for (int nt = 0; nt < 4; nt++) {
                const int cb = wn * 32 + nt * 8 + gq;
                unsigned b0 = __float_as_uint(Bs[cb * LDS_STRIDE + kbase    ]);
                unsigned b1 = __float_as_uint(Bs[cb * LDS_STRIDE + kbase + 4]);
#pragma unroll
                for (int mt = 0; mt < 2; mt++)
                    mma_tf32_sync(acc[mt][nt], a[mt], b0, b1);
            }
        }
    }
}
#endif // !HAVE_TCGEN05

__global__ void __launch_bounds__(256, 1) gru_mma_kernel(
    const float* __restrict__ x, const float* __restrict__ h_prev,
    const float* __restrict__ Wiz, const float* __restrict__ Wir,
    const float* __restrict__ Wih, const float* __restrict__ Whz,
    const float* __restrict__ Whr, const float* __restrict__ Whh,
    const float* __restrict__ biz, const float* __restrict__ bir,
    const float* __restrict__ big, const float* __restrict__ bhz,
    const float* __restrict__ bhr, const float* __restrict__ bhh,
    float* __restrict__ out)
{
#if !HAVE_TCGEN05
    extern __shared__ float smemf[];
    const int tid = threadIdx.x;
    const int lane = tid & 31;
    const int warp = tid >> 5;
    const int wm = warp >> 1;
    const int wn = warp & 1;
    const int gq = lane >> 2;
    const int tg = lane & 3;

    const int rowBase = blockIdx.y * BM;
    const int colBase = blockIdx.x * BN;
    const float* WI[3] = {Wiz, Wir, Wih};
    const float* WH[3] = {Whz, Whr, Whh};

    float accZ[2][4][4], accR[2][4][4], accG[2][4][4], accH[2][4][4];
#pragma unroll
    for (int mt = 0; mt < 2; mt++)
#pragma unroll
        for (int nt = 0; nt < 4; nt++)
#pragma unroll
            for (int r = 0; r < 4; r++) {
                accZ[mt][nt][r] = 0.f; accR[mt][nt][r] = 0.f;
                accG[mt][nt][r] = 0.f; accH[mt][nt][r] = 0.f;
            }

#define ISSUE_LOAD_MMA(s)                                                          \
    do {                                                                           \
        const float* Aptr = ((s) < 32) ? x : h_prev;                               \
        const int k0 = ((s) & 31) * 32;                                            \
        float* st = smemf + ((s) & 1) * STAGE_FLOATS;                              \
        _Pragma("unroll")                                                          \
        for (int i = 0; i < 4; i++) {                                              \
            int lin = tid + i * 256;                                               \
            int r = lin >> 3, c4 = lin & 7;                                        \
            cp_async16f(st + r * LDS_STRIDE + c4 * 4,                              \
                        Aptr + (size_t)(rowBase + r) * I_DIM + k0 + c4 * 4);       \
        }                                                                          \
        _Pragma("unroll")                                                          \
        for (int gt = 0; gt < 3; gt++) {                                           \
            const float* W = ((s) < 32) ? WI[gt] : WH[gt];                         \
            float* bs = st + A_FLOATS + gt * B_FLOATS;                             \
            _Pragma("unroll")                                                      \
            for (int i = 0; i < 2; i++) {                                          \
                int lin = tid + i * 256;                                           \
                int r = lin >> 3, c4 = lin & 7;                                    \
                cp_async16f(bs + r * LDS_STRIDE + c4 * 4,                          \
                            W + (size_t)(colBase + r) * I_DIM + k0 + c4 * 4);      \
            }                                                                      \
        }                                                                          \
        asm volatile("cp.async.commit_group;");                                    \
    } while (0)

    ISSUE_LOAD_MMA(0);

#pragma unroll 1
    for (int s = 0; s < 64; s++) {
        if (s + 1 < 64) {
            ISSUE_LOAD_MMA(s + 1);
            asm volatile("cp.async.wait_group 1;");
        } else {
            asm volatile("cp.async.wait_group 0;");
        }
        __syncthreads();
        const float* st = smemf + (s & 1) * STAGE_FLOATS;
        if (s < 32) compute_step_mma(st, wm, wn, gq, tg, accZ, accR, accG);
        else        compute_step_mma(st, wm, wn, gq, tg, accZ, accR, accH);
        __syncthreads();
    }
#undef ISSUE_LOAD_MMA

    const int colW = colBase + wn * 32;
#pragma unroll
    for (int mt = 0; mt < 2; mt++) {
#pragma unroll
        for (int mh = 0; mh < 2; mh++) {
            const int row = rowBase + wm * 32 + mt * 16 + gq + mh * 8;
            const float* hrow = h_prev + (size_t)row * H_DIM;
            float* orow = out + (size_t)row * H_DIM;
#pragma unroll
            for (int nt = 0; nt < 4; nt++) {
                const int c = colW + nt * 8 + tg * 2;
                float h2[2];
#pragma unroll
                for (int j = 0; j < 2; j++) {
                    const int col = c + j;
                    const int ridx = mh * 2 + j;
                    float zp = accZ[mt][nt][ridx] + biz[col] + bhz[col];
                    float rp = accR[mt][nt][ridx] + bir[col] + bhr[col];
                    float z = 1.f / (1.f + __expf(-zp));
                    float r = 1.f / (1.f + __expf(-rp));
                    float gp = accG[mt][nt][ridx] + big[col] + r * (accH[mt][nt][ridx] + bhh[col]);
                    float g = tanhf(gp);
                    h2[j] = (1.f - z) * g + z * hrow[col];
                }
                *reinterpret_cast<float2*>(orow + c) = make_float2(h2[0], h2[1]);
            }
        }
    }
#endif // !HAVE_TCGEN05
}

// ---------------------------------------------------------------------------
// Launch: main GEMM first, hedge second.
// ---------------------------------------------------------------------------
extern "C" void kernel_launch(void* const* d_in, const int* in_sizes, int n_in,
                              void* d_out, int out_size)
{
    const float* x   = (const float*)d_in[0];
    const float* h   = (const float*)d_in[1];
    const float* Wiz = (const float*)d_in[2];
    const float* biz = (const float*)d_in[3];
    const float* Wir = (const float*)d_in[4];
    const float* bir = (const float*)d_in[5];
    const float* Wih = (const float*)d_in[6];
    const float* big = (const float*)d_in[7];
    const float* Whz = (const float*)d_in[8];
    const float* bhz = (const float*)d_in[9];
    const float* Whr = (const float*)d_in[10];
    const float* bhr = (const float*)d_in[11];
    const float* Whh = (const float*)d_in[12];
    const float* bhh = (const float*)d_in[13];
    float* out = (float*)d_out;

    // 1) Path A: tcgen05 main kernel
    cudaFuncSetAttribute(gru_tc_kernel, cudaFuncAttributeMaxDynamicSharedMemorySize, SMEM_TOTAL_TC);
    {
        dim3 grid(1024, 1);
        gru_tc_kernel<<<grid, 288, SMEM_TOTAL_TC>>>(
            x, h, Wiz, Wir, Wih, Whz, Whr, Whh,
            biz, bir, big, bhz, bhr, bhh, out);
    }

    // 2) Path B hedge (empty cubin on sm_103a)
    cudaFuncSetAttribute(gru_mma_kernel, cudaFuncAttributeMaxDynamicSharedMemorySize, SMEM_BYTES_MMA);
    {
        dim3 grid(H_DIM / BN, B_DIM / BM);
        gru_mma_kernel<<<grid, 256, SMEM_BYTES_MMA>>>(
            x, h, Wiz, Wir, Wih, Whz, Whr, Whh,
            biz, bir, big, bhz, bhr, bhh, out);
    }
}

// round 14
// speedup vs baseline: 1.4697x; 1.0353x over previous
#include <cuda_runtime.h>
#include <cuda.h>
#include <dlfcn.h>
#include <cstdint>
#include <math.h>

#define B_DIM 16384
#define I_DIM 1024
#define H_DIM 1024

// Arch-accelerated feature gate: tcgen05 body only when targeting sm_103a/sm_100a.
#if defined(__CUDA_ARCH__) && (defined(__CUDA_ARCH_FEAT_SM103_ALL) || defined(__CUDA_ARCH_FEAT_SM100_ALL))
#define HAVE_TCGEN05 1
#else
#define HAVE_TCGEN05 0
#endif

__device__ __forceinline__ uint32_t smem_u32(const void* p) {
    uint32_t a;
    asm("{ .reg .u64 t; cvta.to.shared.u64 t, %1; cvt.u32.u64 %0, t; }" : "=r"(a) : "l"(p));
    return a;
}

// ===========================================================================
// PATH A: tcgen05 cg2 tf32 — round-13 config (N=128, NST=4, super-buffer
// EMPTY, per-stage FULL/PAIR, N-fast raster, raw operands + de-bias) with ONE
// change: producers are TMA 2D loads (4 per stage, single thread, expect_tx)
// instead of 2560 cp.async per chunk across 8 warps.
// ===========================================================================
#if HAVE_TCGEN05

#define MBAR_INIT(addr, cnt) \
    asm volatile("mbarrier.init.shared.b64 [%0], %1;" :: "r"(addr), "r"(cnt) : "memory")
#define MBAR_ARRIVE(addr) \
    asm volatile("mbarrier.arrive.shared.b64 _, [%0];" :: "r"(addr) : "memory")
#define MBAR_ARRIVE_RANK0(addr) \
    asm volatile("{\n\t.reg .b32 r;\n\t.reg .b32 z;\n\tmov.b32 z, 0;\n\t" \
                 "mapa.shared::cluster.u32 r, %0, z;\n\t" \
                 "mbarrier.arrive.shared::cluster.b64 _, [r];\n\t}" \
                 :: "r"(addr) : "memory")
#define MBAR_EXPECT_TX(addr, bytes) \
    asm volatile("mbarrier.arrive.expect_tx.shared.b64 _, [%0], %1;" \
                 :: "r"(addr), "r"(bytes) : "memory")
#define MBAR_WAIT(addr, ph) do {                                                   \
    uint32_t _m = (addr); uint32_t _p = (ph); uint32_t _done;                      \
    asm volatile("{\n\t.reg .pred p;\n\t"                                          \
        "mbarrier.try_wait.parity.acquire.cta.shared::cta.b64 p, [%1], %2;\n\t"    \
        "selp.b32 %0, 1, 0, p;\n\t}"                                               \
        : "=r"(_done) : "r"(_m), "r"(_p) : "memory");                              \
    if (!_done) {                                                                  \
        asm volatile("{\n\t.reg .pred P1;\n\t"                                     \
            "WL_%=:\n\t"                                                           \
            "mbarrier.try_wait.parity.acquire.cta.shared::cta.b64 P1, [%0], %1, 0x989680;\n\t" \
            "@P1 bra.uni WD_%=;\n\t"                                               \
            "bra.uni WL_%=;\n\t"                                                   \
            "WD_%=:\n\t}"                                                          \
            :: "r"(_m), "r"(_p) : "memory");                                       \
    }                                                                              \
} while (0)

// 2D TMA load: global -> shared::cta, completion via mbarrier complete_tx.
#define TMA_2D(smem_addr, map, cx, cy, mbar) \
    asm volatile("cp.async.bulk.tensor.2d.shared::cta.global.tile" \
                 ".mbarrier::complete_tx::bytes [%0], [%1, {%2, %3}], [%4];" \
                 :: "r"(smem_addr), "l"(map), "r"(cx), "r"(cy), "r"(mbar) : "memory")

#define ALLOC_CG2(res, n) \
    asm volatile("tcgen05.alloc.cta_group::2.sync.aligned.shared::cta.b32 [%0], %1;" :: "r"(res), "r"(n) : "memory")
#define DEALLOC_CG2(t, n) \
    asm volatile("tcgen05.dealloc.cta_group::2.sync.aligned.b32 %0, %1;" :: "r"(t), "r"(n))
#define RELINQ_CG2() \
    asm volatile("tcgen05.relinquish_alloc_permit.cta_group::2.sync.aligned;")
#define COMMIT_MC(addr) \
    asm volatile("tcgen05.commit.cta_group::2.mbarrier::arrive::one.shared::cluster.multicast::cluster.b64 [%0], %1;" \
                 :: "r"(addr), "h"((uint16_t)3) : "memory")
#define TC_FENCE_BEFORE() asm volatile("tcgen05.fence::before_thread_sync;" ::: "memory")
#define TC_FENCE_AFTER()  asm volatile("tcgen05.fence::after_thread_sync;" ::: "memory")
#define TC_WAIT_LD()      asm volatile("tcgen05.wait::ld.sync.aligned;" ::: "memory")
#define CLUSTER_SYNC_() do { \
    asm volatile("barrier.cluster.arrive.aligned;" ::: "memory"); \
    asm volatile("barrier.cluster.wait.aligned;" ::: "memory"); } while (0)

#define LD_X16(r, a) \
    asm volatile("tcgen05.ld.sync.aligned.32x32b.x16.b32 " \
        "{%0, %1, %2, %3, %4, %5, %6, %7, %8, %9, %10, %11, %12, %13, %14, %15}, [%16];" \
        : "=r"((r)[0]), "=r"((r)[1]), "=r"((r)[2]), "=r"((r)[3]), \
          "=r"((r)[4]), "=r"((r)[5]), "=r"((r)[6]), "=r"((r)[7]), \
          "=r"((r)[8]), "=r"((r)[9]), "=r"((r)[10]), "=r"((r)[11]), \
          "=r"((r)[12]), "=r"((r)[13]), "=r"((r)[14]), "=r"((r)[15]) \
        : "r"(a))

__device__ __forceinline__ void mma_tf32_cg2(uint32_t d, uint64_t ad, uint64_t bd,
                                             uint32_t idesc, uint32_t en) {
    asm volatile(
        "{\n\t.reg .pred p;\n\tsetp.ne.u32 p, %4, 0;\n\t"
        "tcgen05.mma.cta_group::2.kind::tf32 [%0], %1, %2, %3, "
        "{%5, %5, %5, %5, %5, %5, %5, %5}, p;\n\t}"
        :: "r"(d), "l"(ad), "l"(bd), "r"(idesc), "r"(en), "r"(0u)
        : "memory");
}

__device__ __forceinline__ uint64_t sdesc(uint32_t addr) {
    return ((uint64_t)2 << 61) | ((uint64_t)1 << 46) | ((uint64_t)64 << 32) |
           ((uint64_t)1 << 16) | ((addr >> 4) & 0x3FFF);
}

#endif // HAVE_TCGEN05

constexpr int NST = 4;                 // physical 40KB stages (2 per super-buffer)
constexpr int STAGE_BYTES = 40960;     // A 16KB + 3x B 8KB
constexpr int SMEM_STAGE0 = 4096;
constexpr int SMEM_TOTAL_TC = SMEM_STAGE0 + NST * STAGE_BYTES;   // 167936

// idesc: dtype=f32(1)<<4, atype=tf32(2)<<7, btype=tf32(2)<<10, N/8<<17, M/16<<24
constexpr uint32_t IDESC_TF32 = (1u << 4) | (2u << 7) | (2u << 10) | (16u << 17) | (16u << 24);

constexpr int OFF_TMEM  = 0;
constexpr int OFF_FULL  = 16;    // 4 x 8B  (per physical stage; expect_tx)
constexpr int OFF_EMPTY = 48;    // 2 x 8B  (per super-buffer)
constexpr int OFF_PAIR  = 64;    // 4 x 8B  (per physical stage)
constexpr int OFF_DONE  = 96;
constexpr int OFF_BIAS  = 128;   // 512 floats

constexpr uint32_t STAGE_TX = 40960;   // bytes per stage per CTA

// De-bias for double RZ tf32 truncation (both operands raw).
#define TRUNC_DEBIAS 1.000677f

__global__ void __launch_bounds__(288, 1) __cluster_dims__(2, 1, 1)
gru_tc_kernel(const __grid_constant__ CUtensorMap mapX,
              const __grid_constant__ CUtensorMap mapH,
              const __grid_constant__ CUtensorMap mapWiz,
              const __grid_constant__ CUtensorMap mapWir,
              const __grid_constant__ CUtensorMap mapWih,
              const __grid_constant__ CUtensorMap mapWhz,
              const __grid_constant__ CUtensorMap mapWhr,
              const __grid_constant__ CUtensorMap mapWhh,
              const float* __restrict__ h_prev,
              const float* __restrict__ biz, const float* __restrict__ bir,
              const float* __restrict__ big, const float* __restrict__ bhz,
              const float* __restrict__ bhr, const float* __restrict__ bhh,
              float* __restrict__ out)
{
#if HAVE_TCGEN05
    extern __shared__ char smem[];
    const uint32_t sb = smem_u32(smem);
    const int tid = threadIdx.x;
    const uint32_t rank = blockIdx.x & 1;
    // N-fast pair raster (proven)
    const int pair = blockIdx.x >> 1;
    const int colBase  = (pair & 7) * 128;
    const int rowBase  = (pair >> 3) * 256 + (int)rank * 128;
    const int wColBase = colBase + (int)rank * 64;

    if (tid == 0) {
        for (int st = 0; st < NST; st++) {
            MBAR_INIT(sb + OFF_FULL + st * 8, 1);    // expect_tx arrival
            MBAR_INIT(sb + OFF_PAIR + st * 8, 2);
        }
        for (int b = 0; b < 2; b++)
            MBAR_INIT(sb + OFF_EMPTY + b * 8, 1);
        MBAR_INIT(sb + OFF_DONE, 1);
    }
    if (tid >= 256) {
        ALLOC_CG2(sb + OFF_TMEM, 512);
    }
    if (tid < 128) {
        int c = colBase + tid;
        float* bb = (float*)(smem + OFF_BIAS);
        bb[tid]       = biz[c] + bhz[c];
        bb[128 + tid] = bir[c] + bhr[c];
        bb[256 + tid] = big[c];
        bb[384 + tid] = bhh[c];
    }
    __syncthreads();
    uint32_t tmem;
    asm volatile("ld.shared.b32 %0, [%1];" : "=r"(tmem) : "r"(sb + OFF_TMEM));
    CLUSTER_SYNC_();

    if (tid == 0) {
        // ---------- producer: single thread, 4 TMA 2D loads per stage --------
#pragma unroll 1
        for (int s = 0; s < 32; s++) {
            const int b   = s & 1;
            const int pph = 1 ^ ((s >> 1) & 1);
            MBAR_WAIT(sb + OFF_EMPTY + b * 8, pph);
#pragma unroll
            for (int sub = 0; sub < 2; sub++) {
                const int chunk = 2 * s + sub;
                const int st = 2 * b + sub;
                const int k0 = (chunk & 31) * 32;
                const uint32_t stb = sb + SMEM_STAGE0 + st * STAGE_BYTES;
                const uint32_t mb = sb + OFF_FULL + st * 8;
                MBAR_EXPECT_TX(mb, STAGE_TX);
                if (chunk < 32) {
                    TMA_2D(stb, &mapX, k0, rowBase, mb);
                    TMA_2D(stb + 16384,        &mapWiz, k0, wColBase, mb);
                    TMA_2D(stb + 16384 + 8192, &mapWir, k0, wColBase, mb);
                    TMA_2D(stb + 16384 + 16384,&mapWih, k0, wColBase, mb);
                } else {
                    TMA_2D(stb, &mapH, k0, rowBase, mb);
                    TMA_2D(stb + 16384,        &mapWhz, k0, wColBase, mb);
                    TMA_2D(stb + 16384 + 8192, &mapWhr, k0, wColBase, mb);
                    TMA_2D(stb + 16384 + 16384,&mapWhh, k0, wColBase, mb);
                }
            }
        }
    } else if (tid >= 256) {
        // ---------- control: warp 8 — per stage FULL/PAIR, super-buffer commit
        const int lane = tid - 256;
#pragma unroll 1
        for (int s = 0; s < 32; s++) {
            const int b  = s & 1;
            const int ph = (s >> 1) & 1;
#pragma unroll
            for (int sub = 0; sub < 2; sub++) {
                const int st = 2 * b + sub;
                const int chunk = 2 * s + sub;
                MBAR_WAIT(sb + OFF_FULL + st * 8, ph);       // this stage loaded
                if (rank == 0) {
                    if (lane == 0) MBAR_ARRIVE(sb + OFF_PAIR + st * 8);
                    MBAR_WAIT(sb + OFF_PAIR + st * 8, ph);   // both CTAs' stage full
                    if (lane == 0) {
                        const uint32_t stb = sb + SMEM_STAGE0 + st * STAGE_BYTES;
                        const uint64_t aD = sdesc(stb);
                        const uint32_t tG = (chunk < 32) ? (tmem + 256) : (tmem + 384);
#pragma unroll
                        for (int g = 0; g < 3; g++) {
                            const uint64_t bD = sdesc(stb + 16384 + g * 8192);
                            const uint32_t dcol = (g == 0) ? tmem : ((g == 1) ? (tmem + 128) : tG);
#pragma unroll
                            for (int ks = 0; ks < 4; ks++) {
                                uint32_t en = !(ks == 0 && (chunk == 0 || (chunk == 32 && g == 2)));
                                mma_tf32_cg2(dcol, aD + ks * 2, bD + ks * 2, IDESC_TF32, en);
                            }
                        }
                    }
                } else {
                    if (lane == 0) MBAR_ARRIVE_RANK0(sb + OFF_PAIR + st * 8);
                }
            }
            if (rank == 0 && lane == 0)
                COMMIT_MC(sb + OFF_EMPTY + b * 8);   // frees super-buffer in BOTH CTAs
        }
        if (rank == 0 && lane == 0) COMMIT_MC(sb + OFF_DONE);
    }

    // epilogue: warps 0-3 read TMEM, de-bias, fuse activations
    if (tid < 128) {
        MBAR_WAIT(sb + OFF_DONE, 0);
        TC_FENCE_AFTER();
        const int warp = tid >> 5, lane = tid & 31;
        const int grow = rowBase + warp * 32 + lane;
        const float* hrow = h_prev + (size_t)grow * H_DIM + colBase;
        float* orow = out + (size_t)grow * H_DIM + colBase;
        const float* bb = (const float*)(smem + OFF_BIAS);
#pragma unroll 1
        for (int c0 = 0; c0 < 128; c0 += 16) {
            uint32_t rz[16], rr[16], rg[16], rh[16];
            LD_X16(rz, tmem + c0);
            LD_X16(rr, tmem + 128 + c0);
            LD_X16(rg, tmem + 256 + c0);
            LD_X16(rh, tmem + 384 + c0);
            TC_WAIT_LD();
            TC_FENCE_BEFORE();
            float o[16];
#pragma unroll
            for (int j = 0; j < 16; j++) {
                const int cc = c0 + j;
                float az = __uint_as_float(rz[j]) * TRUNC_DEBIAS;
                float ar = __uint_as_float(rr[j]) * TRUNC_DEBIAS;
                float ag = __uint_as_float(rg[j]) * TRUNC_DEBIAS;
                float ah = __uint_as_float(rh[j]) * TRUNC_DEBIAS;
                float z = 1.f / (1.f + __expf(-(az + bb[cc])));
                float r = 1.f / (1.f + __expf(-(ar + bb[128 + cc])));
                float g = tanhf(ag + bb[256 + cc] + r * (ah + bb[384 + cc]));
                o[j] = (1.f - z) * g + z * hrow[cc];
            }
#pragma unroll
            for (int q = 0; q < 4; q++)
                *reinterpret_cast<float4*>(orow + c0 + q * 4) =
                    make_float4(o[q * 4], o[q * 4 + 1], o[q * 4 + 2], o[q * 4 + 3]);
        }
    }

    __syncthreads();
    if (tid >= 256) {
        RELINQ_CG2();
        DEALLOC_CG2(tmem, 512);
    }
    CLUSTER_SYNC_();
#endif // HAVE_TCGEN05
}

// ===========================================================================
// PATH B: mma.sync tf32 fallback (baseline-sm_103 cubin only; hedge).
// ===========================================================================
constexpr int BM = 128;
constexpr int BN = 64;
constexpr int LDS_STRIDE = 36;
constexpr int A_FLOATS = BM * LDS_STRIDE;
constexpr int B_FLOATS = BN * LDS_STRIDE;
constexpr int STAGE_FLOATS = A_FLOATS + 3 * B_FLOATS;
constexpr int SMEM_BYTES_MMA = 2 * STAGE_FLOATS * 4;

#if !HAVE_TCGEN05

__device__ __forceinline__ void cp_async16f(float* dst, const float* src) {
    unsigned d = (unsigned)__cvta_generic_to_shared(dst);
    asm volatile("cp.async.cg.shared.global [%0], [%1], 16;" :: "r"(d), "l"(src));
}

__device__ __forceinline__ void mma_tf32_sync(float d[4], const unsigned a[4], unsigned b0, unsigned b1) {
    asm volatile(
        "mma.sync.aligned.m16n8k8.row.col.f32.tf32.tf32.f32 "
        "{%0,%1,%2,%3}, {%4,%5,%6,%7}, {%8,%9}, {%0,%1,%2,%3};"
        : "+f"(d[0]), "+f"(d[1]), "+f"(d[2]), "+f"(d[3])
        : "r"(a[0]), "r"(a[1]), "r"(a[2]), "r"(a[3]), "r"(b0), "r"(b1));
}

__device__ __forceinline__ void compute_step_mma(
    const float* st, int wm, int wn, int gq, int tg,
    float (&accZ)[2][4][4], float (&accR)[2][4][4], float (&accT)[2][4][4])
{
#pragma unroll
    for (int kk = 0; kk < 4; kk++) {
        unsigned a[2][4];
        const int kbase = kk * 8 + tg;
#pragma unroll
        for (int mt = 0; mt < 2; mt++) {
            const int rb = wm * 32 + mt * 16;
            a[mt][0] = __float_as_uint(st[(rb + gq    ) * LDS_STRIDE + kbase    ]);
            a[mt][1] = __float_as_uint(st[(rb + gq + 8) * LDS_STRIDE + kbase    ]);
            a[mt][2] = __float_as_uint(st[(rb + gq    ) * LDS_STRIDE + kbase + 4]);
            a[mt][3] = __float_as_uint(st[(rb + gq + 8) * LDS_STRIDE + kbase + 4]);
        }
#pragma unroll
        for (int gt = 0; gt < 3; gt++) {
            const float* Bs = st + A_FLOATS + gt * B_FLOATS;
            float (&acc)[2][4][4] = (gt == 0) ? accZ : ((gt == 1) ? accR : accT);
#pragma unroll
            for (int nt = 0; nt < 4; nt++) {
                const int cb = wn * 32 + nt * 8 + gq;
                unsigned b0 = __float_as_uint(Bs[cb * LDS_STRIDE + kbase    ]);
                unsigned b1 = __float_as_uint(Bs[cb * LDS_STRIDE + kbase + 4]);
#pragma unroll
                for (int mt = 0; mt < 2; mt++)
                    mma_tf32_sync(acc[mt][nt], a[mt], b0, b1);
            }
        }
    }
}
#endif // !HAVE_TCGEN05

__global__ void __launch_bounds__(256, 1) gru_mma_kernel(
    const float* __restrict__ x, const float* __restrict__ h_prev,
    const float* __restrict__ Wiz, const float* __restrict__ Wir,
    const float* __restrict__ Wih, const float* __restrict__ Whz,
    const float* __restrict__ Whr, const float* __restrict__ Whh,
    const float* __restrict__ biz, const float* __restrict__ bir,
    const float* __restrict__ big, const float* __restrict__ bhz,
    const float* __restrict__ bhr, const float* __restrict__ bhh,
    float* __restrict__ out)
{
#if !HAVE_TCGEN05
    extern __shared__ float smemf[];
    const int tid = threadIdx.x;
    const int lane = tid & 31;
    const int warp = tid >> 5;
    const int wm = warp >> 1;
    const int wn = warp & 1;
    const int gq = lane >> 2;
    const int tg = lane & 3;

    const int rowBase = blockIdx.y * BM;
    const int colBase = blockIdx.x * BN;
    const float* WI[3] = {Wiz, Wir, Wih};
    const float* WH[3] = {Whz, Whr, Whh};

    float accZ[2][4][4], accR[2][4][4], accG[2][4][4], accH[2][4][4];
#pragma unroll
    for (int mt = 0; mt < 2; mt++)
#pragma unroll
        for (int nt = 0; nt < 4; nt++)
#pragma unroll
            for (int r = 0; r < 4; r++) {
                accZ[mt][nt][r] = 0.f; accR[mt][nt][r] = 0.f;
                accG[mt][nt][r] = 0.f; accH[mt][nt][r] = 0.f;
            }

#define ISSUE_LOAD_MMA(s)                                                          \
    do {                                                                           \
        const float* Aptr = ((s) < 32) ? x : h_prev;                               \
        const int k0 = ((s) & 31) * 32;                                            \
        float* st = smemf + ((s) & 1) * STAGE_FLOATS;                              \
        _Pragma("unroll")                                                          \
        for (int i = 0; i < 4; i++) {                                              \
            int lin = tid + i * 256;                                               \
            int r = lin >> 3, c4 = lin & 7;                                        \
            cp_async16f(st + r * LDS_STRIDE + c4 * 4,                              \
                        Aptr + (size_t)(rowBase + r) * I_DIM + k0 + c4 * 4);       \
        }                                                                          \
        _Pragma("unroll")                                                          \
        for (int gt = 0; gt < 3; gt++) {                                           \
            const float* W = ((s) < 32) ? WI[gt] : WH[gt];                         \
            float* bs = st + A_FLOATS + gt * B_FLOATS;                             \
            _Pragma("unroll")                                                      \
            for (int i = 0; i < 2; i++) {                                          \
                int lin = tid + i * 256;                                           \
                int r = lin >> 3, c4 = lin & 7;                                    \
                cp_async16f(bs + r * LDS_STRIDE + c4 * 4,                          \
                            W + (size_t)(colBase + r) * I_DIM + k0 + c4 * 4);      \
            }                                                                      \
        }                                                                          \
        asm volatile("cp.async.commit_group;");                                    \
    } while (0)

    ISSUE_LOAD_MMA(0);

#pragma unroll 1
    for (int s = 0; s < 64; s++) {
        if (s + 1 < 64) {
            ISSUE_LOAD_MMA(s + 1);
            asm volatile("cp.async.wait_group 1;");
        } else {
            asm volatile("cp.async.wait_group 0;");
        }
        __syncthreads();
        const float* st = smemf + (s & 1) * STAGE_FLOATS;
        if (s < 32) compute_step_mma(st, wm, wn, gq, tg, accZ, accR, accG);
        else        compute_step_mma(st, wm, wn, gq, tg, accZ, accR, accH);
        __syncthreads();
    }
#undef ISSUE_LOAD_MMA

    const int colW = colBase + wn * 32;
#pragma unroll
    for (int mt = 0; mt < 2; mt++) {
#pragma unroll
        for (int mh = 0; mh < 2; mh++) {
            const int row = rowBase + wm * 32 + mt * 16 + gq + mh * 8;
            const float* hrow = h_prev + (size_t)row * H_DIM;
            float* orow = out + (size_t)row * H_DIM;
#pragma unroll
            for (int nt = 0; nt < 4; nt++) {
                const int c = colW + nt * 8 + tg * 2;
                float h2[2];
#pragma unroll
                for (int j = 0; j < 2; j++) {
                    const int col = c + j;
                    const int ridx = mh * 2 + j;
                    float zp = accZ[mt][nt][ridx] + biz[col] + bhz[col];
                    float rp = accR[mt][nt][ridx] + bir[col] + bhr[col];
                    float z = 1.f / (1.f + __expf(-zp));
                    float r = 1.f / (1.f + __expf(-rp));
                    float gp = accG[mt][nt][ridx] + big[col] + r * (accH[mt][nt][ridx] + bhh[col]);
                    float g = tanhf(gp);
                    h2[j] = (1.f - z) * g + z * hrow[col];
                }
                *reinterpret_cast<float2*>(orow + c) = make_float2(h2[0], h2[1]);
            }
        }
    }
#endif // !HAVE_TCGEN05
}

// ---------------------------------------------------------------------------
// Launch: build 8 tensormaps (driver via dlopen), main GEMM first, hedge.
// ---------------------------------------------------------------------------
using TmapEncodeFn = CUresult (*)(
    CUtensorMap*, CUtensorMapDataType, cuuint32_t, void*,
    const cuuint64_t*, const cuuint64_t*, const cuuint32_t*, const cuuint32_t*,
    CUtensorMapInterleave, CUtensorMapSwizzle, CUtensorMapL2promotion,
    CUtensorMapFloatOOBfill);

static void make_map(TmapEncodeFn enc, CUtensorMap* m, const void* ptr,
                     uint64_t rows, uint32_t boxRows) {
    cuuint64_t dims[2]    = {(cuuint64_t)I_DIM, (cuuint64_t)rows};
    cuuint64_t strides[1] = {(cuuint64_t)I_DIM * sizeof(float)};
    cuuint32_t box[2]     = {32u, boxRows};     // 32 f32 = 128B = SW128 atom
    cuuint32_t estr[2]    = {1u, 1u};
    enc(m, CU_TENSOR_MAP_DATA_TYPE_FLOAT32, 2, const_cast<void*>(ptr),
        dims, strides, box, estr,
        CU_TENSOR_MAP_INTERLEAVE_NONE, CU_TENSOR_MAP_SWIZZLE_128B,
        CU_TENSOR_MAP_L2_PROMOTION_L2_128B, CU_TENSOR_MAP_FLOAT_OOB_FILL_NONE);
}

extern "C" void kernel_launch(void* const* d_in, const int* in_sizes, int n_in,
                              void* d_out, int out_size)
{
    const float* x   = (const float*)d_in[0];
    const float* h   = (const float*)d_in[1];
    const float* Wiz = (const float*)d_in[2];
    const float* biz = (const float*)d_in[3];
    const float* Wir = (const float*)d_in[4];
    const float* bir = (const float*)d_in[5];
    const float* Wih = (const float*)d_in[6];
    const float* big = (const float*)d_in[7];
    const float* Whz = (const float*)d_in[8];
    const float* bhz = (const float*)d_in[9];
    const float* Whr = (const float*)d_in[10];
    const float* bhr = (const float*)d_in[11];
    const float* Whh = (const float*)d_in[12];
    const float* bhh = (const float*)d_in[13];
    float* out = (float*)d_out;

    static CUtensorMap mX, mH, mWiz, mWir, mWih, mWhz, mWhr, mWhh;
    {
        void* lib = dlopen("libcuda.so.1", RTLD_NOW | RTLD_GLOBAL);
        TmapEncodeFn enc = lib ? (TmapEncodeFn)dlsym(lib, "cuTensorMapEncodeTiled") : nullptr;
        if (enc) {
            make_map(enc, &mX,   x,   B_DIM, 128);
            make_map(enc, &mH,   h,   B_DIM, 128);
            make_map(enc, &mWiz, Wiz, H_DIM, 64);
            make_map(enc, &mWir, Wir, H_DIM, 64);
            make_map(enc, &mWih, Wih, H_DIM, 64);
            make_map(enc, &mWhz, Whz, H_DIM, 64);
            make_map(enc, &mWhr, Whr, H_DIM, 64);
            make_map(enc, &mWhh, Whh, H_DIM, 64);
        }
    }

    // 1) Path A: tcgen05 main kernel (TMA producers)
    cudaFuncSetAttribute(gru_tc_kernel, cudaFuncAttributeMaxDynamicSharedMemorySize, SMEM_TOTAL_TC);
    {
        dim3 grid(1024, 1);
        gru_tc_kernel<<<grid, 288, SMEM_TOTAL_TC>>>(
            mX, mH, mWiz, mWir, mWih, mWhz, mWhr, mWhh,
            h, biz, bir, big, bhz, bhr, bhh, out);
    }

    // 2) Path B hedge (empty cubin on sm_103a)
    cudaFuncSetAttribute(gru_mma_kernel, cudaFuncAttributeMaxDynamicSharedMemorySize, SMEM_BYTES_MMA);
    {
        dim3 grid(H_DIM / BN, B_DIM / BM);
        gru_mma_kernel<<<grid, 256, SMEM_BYTES_MMA>>>(
            x, h, Wiz, Wir, Wih, Whz, Whr, Whh,
            biz, bir, big, bhz, bhr, bhh, out);
    }
}

// round 15
// speedup vs baseline: 1.4949x; 1.0172x over previous
#include <cuda_runtime.h>
#include <cuda.h>
#include <dlfcn.h>
#include <cstdint>
#include <math.h>

#define B_DIM 16384
#define I_DIM 1024
#define H_DIM 1024

// Arch-accelerated feature gate: tcgen05 body only when targeting sm_103a/sm_100a.
#if defined(__CUDA_ARCH__) && (defined(__CUDA_ARCH_FEAT_SM103_ALL) || defined(__CUDA_ARCH_FEAT_SM100_ALL))
#define HAVE_TCGEN05 1
#else
#define HAVE_TCGEN05 0
#endif

__device__ __forceinline__ uint32_t smem_u32(const void* p) {
    uint32_t a;
    asm("{ .reg .u64 t; cvta.to.shared.u64 t, %1; cvt.u32.u64 %0, t; }" : "=r"(a) : "l"(p));
    return a;
}

// ===========================================================================
// PATH A: tcgen05 cg2 tf32 — round-14 config with ONE change: TMA loads use
// cta_group::2, so BOTH CTAs' complete_tx land on rank0's FULL barrier
// (expect_tx = 2 stages' bytes). The per-stage cross-CTA PAIR round and
// rank1's control loop are eliminated from the dispatch path.
// ===========================================================================
#if HAVE_TCGEN05

#define MBAR_INIT(addr, cnt) \
    asm volatile("mbarrier.init.shared.b64 [%0], %1;" :: "r"(addr), "r"(cnt) : "memory")
#define MBAR_EXPECT_TX(addr, bytes) \
    asm volatile("mbarrier.arrive.expect_tx.shared.b64 _, [%0], %1;" \
                 :: "r"(addr), "r"(bytes) : "memory")
#define MBAR_WAIT(addr, ph) do {                                                   \
    uint32_t _m = (addr); uint32_t _p = (ph); uint32_t _done;                      \
    asm volatile("{\n\t.reg .pred p;\n\t"                                          \
        "mbarrier.try_wait.parity.acquire.cta.shared::cta.b64 p, [%1], %2;\n\t"    \
        "selp.b32 %0, 1, 0, p;\n\t}"                                               \
        : "=r"(_done) : "r"(_m), "r"(_p) : "memory");                              \
    if (!_done) {                                                                  \
        asm volatile("{\n\t.reg .pred P1;\n\t"                                     \
            "WL_%=:\n\t"                                                           \
            "mbarrier.try_wait.parity.acquire.cta.shared::cta.b64 P1, [%0], %1, 0x989680;\n\t" \
            "@P1 bra.uni WD_%=;\n\t"                                               \
            "bra.uni WL_%=;\n\t"                                                   \
            "WD_%=:\n\t}"                                                          \
            :: "r"(_m), "r"(_p) : "memory");                                       \
    }                                                                              \
} while (0)

// cta_group::2 3D TMA: data -> local CTA smem; complete_tx -> LEADER CTA's
// barrier (bit 24 cleared). Both CTAs of the pair execute this.
#define TMA_3D_CG2(smem_addr, map, cx, cy, cz, mbar) \
    asm volatile("{\n\t.reg .b32 lb;\n\t" \
                 "and.b32 lb, %5, 0xFEFFFFFF;\n\t" \
                 "cp.async.bulk.tensor.3d.cta_group::2.shared::cluster.global" \
                 ".tile.mbarrier::complete_tx::bytes " \
                 "[%0], [%1, {%2, %3, %4}], [lb];\n\t}" \
                 :: "r"(smem_addr), "l"(map), "r"(cx), "r"(cy), "r"(cz), \
                    "r"(mbar) : "memory")

#define ALLOC_CG2(res, n) \
    asm volatile("tcgen05.alloc.cta_group::2.sync.aligned.shared::cta.b32 [%0], %1;" :: "r"(res), "r"(n) : "memory")
#define DEALLOC_CG2(t, n) \
    asm volatile("tcgen05.dealloc.cta_group::2.sync.aligned.b32 %0, %1;" :: "r"(t), "r"(n))
#define RELINQ_CG2() \
    asm volatile("tcgen05.relinquish_alloc_permit.cta_group::2.sync.aligned;")
#define COMMIT_MC(addr) \
    asm volatile("tcgen05.commit.cta_group::2.mbarrier::arrive::one.shared::cluster.multicast::cluster.b64 [%0], %1;" \
                 :: "r"(addr), "h"((uint16_t)3) : "memory")
#define TC_FENCE_BEFORE() asm volatile("tcgen05.fence::before_thread_sync;" ::: "memory")
#define TC_FENCE_AFTER()  asm volatile("tcgen05.fence::after_thread_sync;" ::: "memory")
#define TC_WAIT_LD()      asm volatile("tcgen05.wait::ld.sync.aligned;" ::: "memory")
#define CLUSTER_SYNC_() do { \
    asm volatile("barrier.cluster.arrive.aligned;" ::: "memory"); \
    asm volatile("barrier.cluster.wait.aligned;" ::: "memory"); } while (0)

#define LD_X16(r, a) \
    asm volatile("tcgen05.ld.sync.aligned.32x32b.x16.b32 " \
        "{%0, %1, %2, %3, %4, %5, %6, %7, %8, %9, %10, %11, %12, %13, %14, %15}, [%16];" \
        : "=r"((r)[0]), "=r"((r)[1]), "=r"((r)[2]), "=r"((r)[3]), \
          "=r"((r)[4]), "=r"((r)[5]), "=r"((r)[6]), "=r"((r)[7]), \
          "=r"((r)[8]), "=r"((r)[9]), "=r"((r)[10]), "=r"((r)[11]), \
          "=r"((r)[12]), "=r"((r)[13]), "=r"((r)[14]), "=r"((r)[15]) \
        : "r"(a))

__device__ __forceinline__ void mma_tf32_cg2(uint32_t d, uint64_t ad, uint64_t bd,
                                             uint32_t idesc, uint32_t en) {
    asm volatile(
        "{\n\t.reg .pred p;\n\tsetp.ne.u32 p, %4, 0;\n\t"
        "tcgen05.mma.cta_group::2.kind::tf32 [%0], %1, %2, %3, "
        "{%5, %5, %5, %5, %5, %5, %5, %5}, p;\n\t}"
        :: "r"(d), "l"(ad), "l"(bd), "r"(idesc), "r"(en), "r"(0u)
        : "memory");
}

__device__ __forceinline__ uint64_t sdesc(uint32_t addr) {
    return ((uint64_t)2 << 61) | ((uint64_t)1 << 46) | ((uint64_t)64 << 32) |
           ((uint64_t)1 << 16) | ((addr >> 4) & 0x3FFF);
}

#endif // HAVE_TCGEN05

constexpr int NST = 4;                 // physical 40KB stages (2 per super-buffer)
constexpr int STAGE_BYTES = 40960;     // A 16KB + 3x B 8KB
constexpr int SMEM_STAGE0 = 4096;
constexpr int SMEM_TOTAL_TC = SMEM_STAGE0 + NST * STAGE_BYTES;   // 167936

// idesc: dtype=f32(1)<<4, atype=tf32(2)<<7, btype=tf32(2)<<10, N/8<<17, M/16<<24
constexpr uint32_t IDESC_TF32 = (1u << 4) | (2u << 7) | (2u << 10) | (16u << 17) | (16u << 24);

constexpr int OFF_TMEM  = 0;
constexpr int OFF_FULL  = 16;    // 4 x 8B  (per stage; rank0 only, expect_tx both CTAs)
constexpr int OFF_EMPTY = 48;    // 2 x 8B  (per super-buffer; multicast commit)
constexpr int OFF_DONE  = 80;
constexpr int OFF_BIAS  = 128;   // 512 floats

constexpr uint32_t STAGE_TX2 = 2 * 40960;   // both CTAs' bytes per stage

// De-bias for double RZ tf32 truncation (both operands raw).
#define TRUNC_DEBIAS 1.000677f

__global__ void __launch_bounds__(288, 1) __cluster_dims__(2, 1, 1)
gru_tc_kernel(const __grid_constant__ CUtensorMap mapX,
              const __grid_constant__ CUtensorMap mapH,
              const __grid_constant__ CUtensorMap mapWiz,
              const __grid_constant__ CUtensorMap mapWir,
              const __grid_constant__ CUtensorMap mapWih,
              const __grid_constant__ CUtensorMap mapWhz,
              const __grid_constant__ CUtensorMap mapWhr,
              const __grid_constant__ CUtensorMap mapWhh,
              const float* __restrict__ h_prev,
              const float* __restrict__ biz, const float* __restrict__ bir,
              const float* __restrict__ big, const float* __restrict__ bhz,
              const float* __restrict__ bhr, const float* __restrict__ bhh,
              float* __restrict__ out)
{
#if HAVE_TCGEN05
    extern __shared__ char smem[];
    const uint32_t sb = smem_u32(smem);
    const int tid = threadIdx.x;
    const uint32_t rank = blockIdx.x & 1;
    // N-fast pair raster (proven)
    const int pair = blockIdx.x >> 1;
    const int colBase  = (pair & 7) * 128;
    const int rowBase  = (pair >> 3) * 256 + (int)rank * 128;
    const int wColBase = colBase + (int)rank * 64;

    if (tid == 0) {
        for (int st = 0; st < NST; st++)
            MBAR_INIT(sb + OFF_FULL + st * 8, 1);    // rank0: expect_tx arrival
        for (int b = 0; b < 2; b++)
            MBAR_INIT(sb + OFF_EMPTY + b * 8, 1);
        MBAR_INIT(sb + OFF_DONE, 1);
    }
    if (tid >= 256) {
        ALLOC_CG2(sb + OFF_TMEM, 512);
    }
    if (tid < 128) {
        int c = colBase + tid;
        float* bb = (float*)(smem + OFF_BIAS);
        bb[tid]       = biz[c] + bhz[c];
        bb[128 + tid] = bir[c] + bhr[c];
        bb[256 + tid] = big[c];
        bb[384 + tid] = bhh[c];
    }
    __syncthreads();
    uint32_t tmem;
    asm volatile("ld.shared.b32 %0, [%1];" : "=r"(tmem) : "r"(sb + OFF_TMEM));
    CLUSTER_SYNC_();   // peer barriers initialized before any cg2 complete_tx

    if (tid == 0) {
        // ---------- producer: single thread per CTA, cg2 TMA loads -----------
        // Both ranks issue into LOCAL smem; complete_tx all land on rank0's
        // FULL(st). Rank0 additionally arms expect_tx (2 CTAs x 40KB).
#pragma unroll 1
        for (int s = 0; s < 32; s++) {
            const int b   = s & 1;
            const int pph = 1 ^ ((s >> 1) & 1);
            MBAR_WAIT(sb + OFF_EMPTY + b * 8, pph);
#pragma unroll
            for (int sub = 0; sub < 2; sub++) {
                const int chunk = 2 * s + sub;
                const int st = 2 * b + sub;
                const int k0 = (chunk & 31) * 32;
                const uint32_t stb = sb + SMEM_STAGE0 + st * STAGE_BYTES;
                const uint32_t mb = sb + OFF_FULL + st * 8;
                if (rank == 0) MBAR_EXPECT_TX(mb, STAGE_TX2);
                if (chunk < 32) {
                    TMA_3D_CG2(stb, &mapX, k0, rowBase, 0, mb);
                    TMA_3D_CG2(stb + 16384,         &mapWiz, k0, wColBase, 0, mb);
                    TMA_3D_CG2(stb + 16384 + 8192,  &mapWir, k0, wColBase, 0, mb);
                    TMA_3D_CG2(stb + 16384 + 16384, &mapWih, k0, wColBase, 0, mb);
                } else {
                    TMA_3D_CG2(stb, &mapH, k0, rowBase, 0, mb);
                    TMA_3D_CG2(stb + 16384,         &mapWhz, k0, wColBase, 0, mb);
                    TMA_3D_CG2(stb + 16384 + 8192,  &mapWhr, k0, wColBase, 0, mb);
                    TMA_3D_CG2(stb + 16384 + 16384, &mapWhh, k0, wColBase, 0, mb);
                }
            }
        }
    } else if (tid >= 256 && rank == 0) {
        // ---------- control: warp 8 on rank0 ONLY (no PAIR round) -------------
        const int lane = tid - 256;
#pragma unroll 1
        for (int s = 0; s < 32; s++) {
            const int b  = s & 1;
            const int ph = (s >> 1) & 1;
#pragma unroll
            for (int sub = 0; sub < 2; sub++) {
                const int st = 2 * b + sub;
                const int chunk = 2 * s + sub;
                MBAR_WAIT(sb + OFF_FULL + st * 8, ph);   // BOTH CTAs' data landed
                if (lane == 0) {
                    const uint32_t stb = sb + SMEM_STAGE0 + st * STAGE_BYTES;
                    const uint64_t aD = sdesc(stb);
                    const uint32_t tG = (chunk < 32) ? (tmem + 256) : (tmem + 384);
#pragma unroll
                    for (int g = 0; g < 3; g++) {
                        const uint64_t bD = sdesc(stb + 16384 + g * 8192);
                        const uint32_t dcol = (g == 0) ? tmem : ((g == 1) ? (tmem + 128) : tG);
#pragma unroll
                        for (int ks = 0; ks < 4; ks++) {
                            uint32_t en = !(ks == 0 && (chunk == 0 || (chunk == 32 && g == 2)));
                            mma_tf32_cg2(dcol, aD + ks * 2, bD + ks * 2, IDESC_TF32, en);
                        }
                    }
                }
            }
            if (lane == 0)
                COMMIT_MC(sb + OFF_EMPTY + b * 8);   // frees super-buffer in BOTH CTAs
        }
        if (lane == 0) COMMIT_MC(sb + OFF_DONE);
    }

    // epilogue: warps 0-3 read TMEM, de-bias, fuse activations
    if (tid < 128) {
        MBAR_WAIT(sb + OFF_DONE, 0);
        TC_FENCE_AFTER();
        const int warp = tid >> 5, lane = tid & 31;
        const int grow = rowBase + warp * 32 + lane;
        const float* hrow = h_prev + (size_t)grow * H_DIM + colBase;
        float* orow = out + (size_t)grow * H_DIM + colBase;
        const float* bb = (const float*)(smem + OFF_BIAS);
#pragma unroll 1
        for (int c0 = 0; c0 < 128; c0 += 16) {
            uint32_t rz[16], rr[16], rg[16], rh[16];
            LD_X16(rz, tmem + c0);
            LD_X16(rr, tmem + 128 + c0);
            LD_X16(rg, tmem + 256 + c0);
            LD_X16(rh, tmem + 384 + c0);
            TC_WAIT_LD();
            TC_FENCE_BEFORE();
            float o[16];
#pragma unroll
            for (int j = 0; j < 16; j++) {
                const int cc = c0 + j;
                float az = __uint_as_float(rz[j]) * TRUNC_DEBIAS;
                float ar = __uint_as_float(rr[j]) * TRUNC_DEBIAS;
                float ag = __uint_as_float(rg[j]) * TRUNC_DEBIAS;
                float ah = __uint_as_float(rh[j]) * TRUNC_DEBIAS;
                float z = 1.f / (1.f + __expf(-(az + bb[cc])));
                float r = 1.f / (1.f + __expf(-(ar + bb[128 + cc])));
                float g = tanhf(ag + bb[256 + cc] + r * (ah + bb[384 + cc]));
                o[j] = (1.f - z) * g + z * hrow[cc];
            }
#pragma unroll
            for (int q = 0; q < 4; q++)
                *reinterpret_cast<float4*>(orow + c0 + q * 4) =
                    make_float4(o[q * 4], o[q * 4 + 1], o[q * 4 + 2], o[q * 4 + 3]);
        }
    }

    __syncthreads();
    if (tid >= 256) {
        RELINQ_CG2();
        DEALLOC_CG2(tmem, 512);
    }
    CLUSTER_SYNC_();   // no CTA exits while peer's cg2 TMA/MMA may touch it
#endif // HAVE_TCGEN05
}

// ===========================================================================
// PATH B: mma.sync tf32 fallback (baseline-sm_103 cubin only; hedge).
// ===========================================================================
constexpr int BM = 128;
constexpr int BN = 64;
constexpr int LDS_STRIDE = 36;
constexpr int A_FLOATS = BM * LDS_STRIDE;
constexpr int B_FLOATS = BN * LDS_STRIDE;
constexpr int STAGE_FLOATS = A_FLOATS + 3 * B_FLOATS;
constexpr int SMEM_BYTES_MMA = 2 * STAGE_FLOATS * 4;

#if !HAVE_TCGEN05

__device__ __forceinline__ void cp_async16f(float* dst, const float* src) {
    unsigned d = (unsigned)__cvta_generic_to_shared(dst);
    asm volatile("cp.async.cg.shared.global [%0], [%1], 16;" :: "r"(d), "l"(src));
}

__device__ __forceinline__ void mma_tf32_sync(float d[4], const unsigned a[4], unsigned b0, unsigned b1) {
    asm volatile(
        "mma.sync.aligned.m16n8k8.row.col.f32.tf32.tf32.f32 "
        "{%0,%1,%2,%3}, {%4,%5,%6,%7}, {%8,%9}, {%0,%1,%2,%3};"
        : "+f"(d[0]), "+f"(d[1]), "+f"(d[2]), "+f"(d[3])
        : "r"(a[0]), "r"(a[1]), "r"(a[2]), "r"(a[3]), "r"(b0), "r"(b1));
}

__device__ __forceinline__ void compute_step_mma(
    const float* st, int wm, int wn, int gq, int tg,
    float (&accZ)[2][4][4], float (&accR)[2][4][4], float (&accT)[2][4][4])
{
#pragma unroll
    for (int kk = 0; kk < 4; kk++) {
        unsigned a[2][4];
        const int kbase = kk * 8 + tg;
#pragma unroll
        for (int mt = 0; mt < 2; mt++) {
            const int rb = wm * 32 + mt * 16;
            a[mt][0] = __float_as_uint(st[(rb + gq    ) * LDS_STRIDE + kbase    ]);
            a[mt][1] = __float_as_uint(st[(rb + gq + 8) * LDS_STRIDE + kbase    ]);
            a[mt][2] = __float_as_uint(st[(rb + gq    ) * LDS_STRIDE + kbase + 4]);
            a[mt][3] = __float_as_uint(st[(rb + gq + 8) * LDS_STRIDE + kbase + 4]);
        }
#pragma unroll
        for (int gt = 0; gt < 3; gt++) {
            const float* Bs = st + A_FLOATS + gt * B_FLOATS;
            float (&acc)[2][4][4] = (gt == 0) ? accZ : ((gt == 1) ? accR : accT);
#pragma unroll
            for (int nt = 0; nt < 4; nt++) {
                const int cb = wn * 32 + nt * 8 + gq;
                unsigned b0 = __float_as_uint(Bs[cb * LDS_STRIDE + kbase    ]);
                unsigned b1 = __float_as_uint(Bs[cb * LDS_STRIDE + kbase + 4]);
#pragma unroll
                for (int mt = 0; mt < 2; mt++)
                    mma_tf32_sync(acc[mt][nt], a[mt], b0, b1);
            }
        }
    }
}
#endif // !HAVE_TCGEN05

__global__ void __launch_bounds__(256, 1) gru_mma_kernel(
    const float* __restrict__ x, const float* __restrict__ h_prev,
    const float* __restrict__ Wiz, const float* __restrict__ Wir,
    const float* __restrict__ Wih, const float* __restrict__ Whz,
    const float* __restrict__ Whr, const float* __restrict__ Whh,
    const float* __restrict__ biz, const float* __restrict__ bir,
    const float* __restrict__ big, const float* __restrict__ bhz,
    const float* __restrict__ bhr, const float* __restrict__ bhh,
    float* __restrict__ out)
{
#if !HAVE_TCGEN05
    extern __shared__ float smemf[];
    const int tid = threadIdx.x;
    const int lane = tid & 31;
    const int warp = tid >> 5;
    const int wm = warp >> 1;
    const int wn = warp & 1;
    const int gq = lane >> 2;
    const int tg = lane & 3;

    const int rowBase = blockIdx.y * BM;
    const int colBase = blockIdx.x * BN;
    const float* WI[3] = {Wiz, Wir, Wih};
    const float* WH[3] = {Whz, Whr, Whh};

    float accZ[2][4][4], accR[2][4][4], accG[2][4][4], accH[2][4][4];
#pragma unroll
    for (int mt = 0; mt < 2; mt++)
#pragma unroll
        for (int nt = 0; nt < 4; nt++)
#pragma unroll
            for (int r = 0; r < 4; r++) {
                accZ[mt][nt][r] = 0.f; accR[mt][nt][r] = 0.f;
                accG[mt][nt][r] = 0.f; accH[mt][nt][r] = 0.f;
            }

#define ISSUE_LOAD_MMA(s)                                                          \
    do {                                                                           \
        const float* Aptr = ((s) < 32) ? x : h_prev;                               \
        const int k0 = ((s) & 31) * 32;                                            \
        float* st = smemf + ((s) & 1) * STAGE_FLOATS;                              \
        _Pragma("unroll")                                                          \
        for (int i = 0; i < 4; i++) {                                              \
            int lin = tid + i * 256;                                               \
            int r = lin >> 3, c4 = lin & 7;                                        \
            cp_async16f(st + r * LDS_STRIDE + c4 * 4,                              \
                        Aptr + (size_t)(rowBase + r) * I_DIM + k0 + c4 * 4);       \
        }                                                                          \
        _Pragma("unroll")                                                          \
        for (int gt = 0; gt < 3; gt++) {                                           \
            const float* W = ((s) < 32) ? WI[gt] : WH[gt];                         \
            float* bs = st + A_FLOATS + gt * B_FLOATS;                             \
            _Pragma("unroll")                                                      \
            for (int i = 0; i < 2; i++) {                                          \
                int lin = tid + i * 256;                                           \
                int r = lin >> 3, c4 = lin & 7;                                    \
                cp_async16f(bs + r * LDS_STRIDE + c4 * 4,                          \
                            W + (size_t)(colBase + r) * I_DIM + k0 + c4 * 4);      \
            }                                                                      \
        }                                                                          \
        asm volatile("cp.async.commit_group;");                                    \
    } while (0)

    ISSUE_LOAD_MMA(0);

#pragma unroll 1
    for (int s = 0; s < 64; s++) {
        if (s + 1 < 64) {
            ISSUE_LOAD_MMA(s + 1);
            asm volatile("cp.async.wait_group 1;");
        } else {
            asm volatile("cp.async.wait_group 0;");
        }
        __syncthreads();
        const float* st = smemf + (s & 1) * STAGE_FLOATS;
        if (s < 32) compute_step_mma(st, wm, wn, gq, tg, accZ, accR, accG);
        else        compute_step_mma(st, wm, wn, gq, tg, accZ, accR, accH);
        __syncthreads();
    }
#undef ISSUE_LOAD_MMA

    const int colW = colBase + wn * 32;
#pragma unroll
    for (int mt = 0; mt < 2; mt++) {
#pragma unroll
        for (int mh = 0; mh < 2; mh++) {
            const int row = rowBase + wm * 32 + mt * 16 + gq + mh * 8;
            const float* hrow = h_prev + (size_t)row * H_DIM;
            float* orow = out + (size_t)row * H_DIM;
#pragma unroll
            for (int nt = 0; nt < 4; nt++) {
                const int c = colW + nt * 8 + tg * 2;
                float h2[2];
#pragma unroll
                for (int j = 0; j < 2; j++) {
                    const int col = c + j;
                    const int ridx = mh * 2 + j;
                    float zp = accZ[mt][nt][ridx] + biz[col] + bhz[col];
                    float rp = accR[mt][nt][ridx] + bir[col] + bhr[col];
                    float z = 1.f / (1.f + __expf(-zp));
                    float r = 1.f / (1.f + __expf(-rp));
                    float gp = accG[mt][nt][ridx] + big[col] + r * (accH[mt][nt][ridx] + bhh[col]);
                    float g = tanhf(gp);
                    h2[j] = (1.f - z) * g + z * hrow[col];
                }
                *reinterpret_cast<float2*>(orow + c) = make_float2(h2[0], h2[1]);
            }
        }
    }
#endif // !HAVE_TCGEN05
}

// ---------------------------------------------------------------------------
// Launch: build 8 3D tensormaps (driver via dlopen), main GEMM first, hedge.
// ---------------------------------------------------------------------------
using TmapEncodeFn = CUresult (*)(
    CUtensorMap*, CUtensorMapDataType, cuuint32_t, void*,
    const cuuint64_t*, const cuuint64_t*, const cuuint32_t*, const cuuint32_t*,
    CUtensorMapInterleave, CUtensorMapSwizzle, CUtensorMapL2promotion,
    CUtensorMapFloatOOBfill);

static void make_map(TmapEncodeFn enc, CUtensorMap* m, const void* ptr,
                     uint64_t rows, uint32_t boxRows) {
    cuuint64_t dims[3]    = {(cuuint64_t)I_DIM, (cuuint64_t)rows, 1};
    cuuint64_t strides[2] = {(cuuint64_t)I_DIM * sizeof(float),
                             (cuuint64_t)rows * I_DIM * sizeof(float)};
    cuuint32_t box[3]     = {32u, boxRows, 1u};   // 32 f32 = 128B = SW128 atom
    cuuint32_t estr[3]    = {1u, 1u, 1u};
    enc(m, CU_TENSOR_MAP_DATA_TYPE_FLOAT32, 3, const_cast<void*>(ptr),
        dims, strides, box, estr,
        CU_TENSOR_MAP_INTERLEAVE_NONE, CU_TENSOR_MAP_SWIZZLE_128B,
        CU_TENSOR_MAP_L2_PROMOTION_L2_128B, CU_TENSOR_MAP_FLOAT_OOB_FILL_NONE);
}

extern "C" void kernel_launch(void* const* d_in, const int* in_sizes, int n_in,
                              void* d_out, int out_size)
{
    const float* x   = (const float*)d_in[0];
    const float* h   = (const float*)d_in[1];
    const float* Wiz = (const float*)d_in[2];
    const float* biz = (const float*)d_in[3];
    const float* Wir = (const float*)d_in[4];
    const float* bir = (const float*)d_in[5];
    const float* Wih = (const float*)d_in[6];
    const float* big = (const float*)d_in[7];
    const float* Whz = (const float*)d_in[8];
    const float* bhz = (const float*)d_in[9];
    const float* Whr = (const float*)d_in[10];
    const float* bhr = (const float*)d_in[11];
    const float* Whh = (const float*)d_in[12];
    const float* bhh = (const float*)d_in[13];
    float* out = (float*)d_out;

    static CUtensorMap mX, mH, mWiz, mWir, mWih, mWhz, mWhr, mWhh;
    {
        void* lib = dlopen("libcuda.so.1", RTLD_NOW | RTLD_GLOBAL);
        TmapEncodeFn enc = lib ? (TmapEncodeFn)dlsym(lib, "cuTensorMapEncodeTiled") : nullptr;
        if (enc) {
            make_map(enc, &mX,   x,   B_DIM, 128);
            make_map(enc, &mH,   h,   B_DIM, 128);
            make_map(enc, &mWiz, Wiz, H_DIM, 64);
            make_map(enc, &mWir, Wir, H_DIM, 64);
            make_map(enc, &mWih, Wih, H_DIM, 64);
            make_map(enc, &mWhz, Whz, H_DIM, 64);
            make_map(enc, &mWhr, Whr, H_DIM, 64);
            make_map(enc, &mWhh, Whh, H_DIM, 64);
        }
    }

    // 1) Path A: tcgen05 main kernel (cg2 TMA producers, no PAIR round)
    cudaFuncSetAttribute(gru_tc_kernel, cudaFuncAttributeMaxDynamicSharedMemorySize, SMEM_TOTAL_TC);
    {
        dim3 grid(1024, 1);
        gru_tc_kernel<<<grid, 288, SMEM_TOTAL_TC>>>(
            mX, mH, mWiz, mWir, mWih, mWhz, mWhr, mWhh,
            h, biz, bir, big, bhz, bhr, bhh, out);
    }

    // 2) Path B hedge (empty cubin on sm_103a)
    cudaFuncSetAttribute(gru_mma_kernel, cudaFuncAttributeMaxDynamicSharedMemorySize, SMEM_BYTES_MMA);
    {
        dim3 grid(H_DIM / BN, B_DIM / BM);
        gru_mma_kernel<<<grid, 256, SMEM_BYTES_MMA>>>(
            x, h, Wiz, Wir, Wih, Whz, Whr, Whh,
            biz, bir, big, bhz, bhr, bhh, out);
    }
}

// round 16
// speedup vs baseline: 1.5100x; 1.0101x over previous
#include <cuda_runtime.h>
#include <cuda.h>
#include <dlfcn.h>
#include <cstdint>
#include <math.h>

#define B_DIM 16384
#define I_DIM 1024
#define H_DIM 1024

// tcgen05 requires an arch-accelerated target; all bench evidence (rounds 3-15)
// confirms the executing cubin is sm_103a, so the kernel is unconditional now.
#if defined(__CUDA_ARCH__) && (defined(__CUDA_ARCH_FEAT_SM103_ALL) || defined(__CUDA_ARCH_FEAT_SM100_ALL))
#define HAVE_TCGEN05 1
#else
#define HAVE_TCGEN05 0
#endif

__device__ __forceinline__ uint32_t smem_u32(const void* p) {
    uint32_t a;
    asm("{ .reg .u64 t; cvta.to.shared.u64 t, %1; cvt.u32.u64 %0, t; }" : "=r"(a) : "l"(p));
    return a;
}

// ===========================================================================
// tcgen05 cg2 tf32 GRU — round-15 kernel, byte-identical mainloop:
// N=128 tiles, NST=4 stages (2 super-buffers), N-fast raster, cg2 TMA
// producers (complete_tx -> leader barrier; no PAIR round), raw fp32 operands
// with scalar de-bias, fused activation epilogue.
// ===========================================================================
#if HAVE_TCGEN05

#define MBAR_INIT(addr, cnt) \
    asm volatile("mbarrier.init.shared.b64 [%0], %1;" :: "r"(addr), "r"(cnt) : "memory")
#define MBAR_EXPECT_TX(addr, bytes) \
    asm volatile("mbarrier.arrive.expect_tx.shared.b64 _, [%0], %1;" \
                 :: "r"(addr), "r"(bytes) : "memory")
#define MBAR_WAIT(addr, ph) do {                                                   \
    uint32_t _m = (addr); uint32_t _p = (ph); uint32_t _done;                      \
    asm volatile("{\n\t.reg .pred p;\n\t"                                          \
        "mbarrier.try_wait.parity.acquire.cta.shared::cta.b64 p, [%1], %2;\n\t"    \
        "selp.b32 %0, 1, 0, p;\n\t}"                                               \
        : "=r"(_done) : "r"(_m), "r"(_p) : "memory");                              \
    if (!_done) {                                                                  \
        asm volatile("{\n\t.reg .pred P1;\n\t"                                     \
            "WL_%=:\n\t"                                                           \
            "mbarrier.try_wait.parity.acquire.cta.shared::cta.b64 P1, [%0], %1, 0x989680;\n\t" \
            "@P1 bra.uni WD_%=;\n\t"                                               \
            "bra.uni WL_%=;\n\t"                                                   \
            "WD_%=:\n\t}"                                                          \
            :: "r"(_m), "r"(_p) : "memory");                                       \
    }                                                                              \
} while (0)

// cta_group::2 3D TMA: data -> local CTA smem; complete_tx -> LEADER CTA's
// barrier (bit 24 cleared). Both CTAs of the pair execute this.
#define TMA_3D_CG2(smem_addr, map, cx, cy, cz, mbar) \
    asm volatile("{\n\t.reg .b32 lb;\n\t" \
                 "and.b32 lb, %5, 0xFEFFFFFF;\n\t" \
                 "cp.async.bulk.tensor.3d.cta_group::2.shared::cluster.global" \
                 ".tile.mbarrier::complete_tx::bytes " \
                 "[%0], [%1, {%2, %3, %4}], [lb];\n\t}" \
                 :: "r"(smem_addr), "l"(map), "r"(cx), "r"(cy), "r"(cz), \
                    "r"(mbar) : "memory")

#define ALLOC_CG2(res, n) \
    asm volatile("tcgen05.alloc.cta_group::2.sync.aligned.shared::cta.b32 [%0], %1;" :: "r"(res), "r"(n) : "memory")
#define DEALLOC_CG2(t, n) \
    asm volatile("tcgen05.dealloc.cta_group::2.sync.aligned.b32 %0, %1;" :: "r"(t), "r"(n))
#define RELINQ_CG2() \
    asm volatile("tcgen05.relinquish_alloc_permit.cta_group::2.sync.aligned;")
#define COMMIT_MC(addr) \
    asm volatile("tcgen05.commit.cta_group::2.mbarrier::arrive::one.shared::cluster.multicast::cluster.b64 [%0], %1;" \
                 :: "r"(addr), "h"((uint16_t)3) : "memory")
#define TC_FENCE_BEFORE() asm volatile("tcgen05.fence::before_thread_sync;" ::: "memory")
#define TC_FENCE_AFTER()  asm volatile("tcgen05.fence::after_thread_sync;" ::: "memory")
#define TC_WAIT_LD()      asm volatile("tcgen05.wait::ld.sync.aligned;" ::: "memory")
#define CLUSTER_SYNC_() do { \
    asm volatile("barrier.cluster.arrive.aligned;" ::: "memory"); \
    asm volatile("barrier.cluster.wait.aligned;" ::: "memory"); } while (0)

#define LD_X16(r, a) \
    asm volatile("tcgen05.ld.sync.aligned.32x32b.x16.b32 " \
        "{%0, %1, %2, %3, %4, %5, %6, %7, %8, %9, %10, %11, %12, %13, %14, %15}, [%16];" \
        : "=r"((r)[0]), "=r"((r)[1]), "=r"((r)[2]), "=r"((r)[3]), \
          "=r"((r)[4]), "=r"((r)[5]), "=r"((r)[6]), "=r"((r)[7]), \
          "=r"((r)[8]), "=r"((r)[9]), "=r"((r)[10]), "=r"((r)[11]), \
          "=r"((r)[12]), "=r"((r)[13]), "=r"((r)[14]), "=r"((r)[15]) \
        : "r"(a))

__device__ __forceinline__ void mma_tf32_cg2(uint32_t d, uint64_t ad, uint64_t bd,
                                             uint32_t idesc, uint32_t en) {
    asm volatile(
        "{\n\t.reg .pred p;\n\tsetp.ne.u32 p, %4, 0;\n\t"
        "tcgen05.mma.cta_group::2.kind::tf32 [%0], %1, %2, %3, "
        "{%5, %5, %5, %5, %5, %5, %5, %5}, p;\n\t}"
        :: "r"(d), "l"(ad), "l"(bd), "r"(idesc), "r"(en), "r"(0u)
        : "memory");
}

__device__ __forceinline__ uint64_t sdesc(uint32_t addr) {
    return ((uint64_t)2 << 61) | ((uint64_t)1 << 46) | ((uint64_t)64 << 32) |
           ((uint64_t)1 << 16) | ((addr >> 4) & 0x3FFF);
}

#endif // HAVE_TCGEN05

constexpr int NST = 4;                 // physical 40KB stages (2 per super-buffer)
constexpr int STAGE_BYTES = 40960;     // A 16KB + 3x B 8KB
constexpr int SMEM_STAGE0 = 4096;
constexpr int SMEM_TOTAL_TC = SMEM_STAGE0 + NST * STAGE_BYTES;   // 167936

// idesc: dtype=f32(1)<<4, atype=tf32(2)<<7, btype=tf32(2)<<10, N/8<<17, M/16<<24
constexpr uint32_t IDESC_TF32 = (1u << 4) | (2u << 7) | (2u << 10) | (16u << 17) | (16u << 24);

constexpr int OFF_TMEM  = 0;
constexpr int OFF_FULL  = 16;    // 4 x 8B  (per stage; rank0 only, expect_tx both CTAs)
constexpr int OFF_EMPTY = 48;    // 2 x 8B  (per super-buffer; multicast commit)
constexpr int OFF_DONE  = 80;
constexpr int OFF_BIAS  = 128;   // 512 floats

constexpr uint32_t STAGE_TX2 = 2 * 40960;   // both CTAs' bytes per stage

// De-bias for double RZ tf32 truncation (both operands raw).
#define TRUNC_DEBIAS 1.000677f

__global__ void __launch_bounds__(288, 1) __cluster_dims__(2, 1, 1)
gru_tc_kernel(const __grid_constant__ CUtensorMap mapX,
              const __grid_constant__ CUtensorMap mapH,
              const __grid_constant__ CUtensorMap mapWiz,
              const __grid_constant__ CUtensorMap mapWir,
              const __grid_constant__ CUtensorMap mapWih,
              const __grid_constant__ CUtensorMap mapWhz,
              const __grid_constant__ CUtensorMap mapWhr,
              const __grid_constant__ CUtensorMap mapWhh,
              const float* __restrict__ h_prev,
              const float* __restrict__ biz, const float* __restrict__ bir,
              const float* __restrict__ big, const float* __restrict__ bhz,
              const float* __restrict__ bhr, const float* __restrict__ bhh,
              float* __restrict__ out)
{
#if HAVE_TCGEN05
    extern __shared__ char smem[];
    const uint32_t sb = smem_u32(smem);
    const int tid = threadIdx.x;
    const uint32_t rank = blockIdx.x & 1;
    // N-fast pair raster (proven)
    const int pair = blockIdx.x >> 1;
    const int colBase  = (pair & 7) * 128;
    const int rowBase  = (pair >> 3) * 256 + (int)rank * 128;
    const int wColBase = colBase + (int)rank * 64;

    if (tid == 0) {
        for (int st = 0; st < NST; st++)
            MBAR_INIT(sb + OFF_FULL + st * 8, 1);    // rank0: expect_tx arrival
        for (int b = 0; b < 2; b++)
            MBAR_INIT(sb + OFF_EMPTY + b * 8, 1);
        MBAR_INIT(sb + OFF_DONE, 1);
    }
    if (tid >= 256) {
        ALLOC_CG2(sb + OFF_TMEM, 512);
    }
    if (tid < 128) {
        int c = colBase + tid;
        float* bb = (float*)(smem + OFF_BIAS);
        bb[tid]       = biz[c] + bhz[c];
        bb[128 + tid] = bir[c] + bhr[c];
        bb[256 + tid] = big[c];
        bb[384 + tid] = bhh[c];
    }
    __syncthreads();
    uint32_t tmem;
    asm volatile("ld.shared.b32 %0, [%1];" : "=r"(tmem) : "r"(sb + OFF_TMEM));
    CLUSTER_SYNC_();   // peer barriers initialized before any cg2 complete_tx

    if (tid == 0) {
        // ---------- producer: single thread per CTA, cg2 TMA loads -----------
#pragma unroll 1
        for (int s = 0; s < 32; s++) {
            const int b   = s & 1;
            const int pph = 1 ^ ((s >> 1) & 1);
            MBAR_WAIT(sb + OFF_EMPTY + b * 8, pph);
#pragma unroll
            for (int sub = 0; sub < 2; sub++) {
                const int chunk = 2 * s + sub;
                const int st = 2 * b + sub;
                const int k0 = (chunk & 31) * 32;
                const uint32_t stb = sb + SMEM_STAGE0 + st * STAGE_BYTES;
                const uint32_t mb = sb + OFF_FULL + st * 8;
                if (rank == 0) MBAR_EXPECT_TX(mb, STAGE_TX2);
                if (chunk < 32) {
                    TMA_3D_CG2(stb, &mapX, k0, rowBase, 0, mb);
                    TMA_3D_CG2(stb + 16384,         &mapWiz, k0, wColBase, 0, mb);
                    TMA_3D_CG2(stb + 16384 + 8192,  &mapWir, k0, wColBase, 0, mb);
                    TMA_3D_CG2(stb + 16384 + 16384, &mapWih, k0, wColBase, 0, mb);
                } else {
                    TMA_3D_CG2(stb, &mapH, k0, rowBase, 0, mb);
                    TMA_3D_CG2(stb + 16384,         &mapWhz, k0, wColBase, 0, mb);
                    TMA_3D_CG2(stb + 16384 + 8192,  &mapWhr, k0, wColBase, 0, mb);
                    TMA_3D_CG2(stb + 16384 + 16384, &mapWhh, k0, wColBase, 0, mb);
                }
            }
        }
    } else if (tid >= 256 && rank == 0) {
        // ---------- control: warp 8 on rank0 ONLY -----------------------------
        const int lane = tid - 256;
#pragma unroll 1
        for (int s = 0; s < 32; s++) {
            const int b  = s & 1;
            const int ph = (s >> 1) & 1;
#pragma unroll
            for (int sub = 0; sub < 2; sub++) {
                const int st = 2 * b + sub;
                const int chunk = 2 * s + sub;
                MBAR_WAIT(sb + OFF_FULL + st * 8, ph);   // BOTH CTAs' data landed
                if (lane == 0) {
                    const uint32_t stb = sb + SMEM_STAGE0 + st * STAGE_BYTES;
                    const uint64_t aD = sdesc(stb);
                    const uint32_t tG = (chunk < 32) ? (tmem + 256) : (tmem + 384);
#pragma unroll
                    for (int g = 0; g < 3; g++) {
                        const uint64_t bD = sdesc(stb + 16384 + g * 8192);
                        const uint32_t dcol = (g == 0) ? tmem : ((g == 1) ? (tmem + 128) : tG);
#pragma unroll
                        for (int ks = 0; ks < 4; ks++) {
                            uint32_t en = !(ks == 0 && (chunk == 0 || (chunk == 32 && g == 2)));
                            mma_tf32_cg2(dcol, aD + ks * 2, bD + ks * 2, IDESC_TF32, en);
                        }
                    }
                }
            }
            if (lane == 0)
                COMMIT_MC(sb + OFF_EMPTY + b * 8);   // frees super-buffer in BOTH CTAs
        }
        if (lane == 0) COMMIT_MC(sb + OFF_DONE);
    }

    // epilogue: warps 0-3 read TMEM, de-bias, fuse activations
    if (tid < 128) {
        MBAR_WAIT(sb + OFF_DONE, 0);
        TC_FENCE_AFTER();
        const int warp = tid >> 5, lane = tid & 31;
        const int grow = rowBase + warp * 32 + lane;
        const float* hrow = h_prev + (size_t)grow * H_DIM + colBase;
        float* orow = out + (size_t)grow * H_DIM + colBase;
        const float* bb = (const float*)(smem + OFF_BIAS);
#pragma unroll 1
        for (int c0 = 0; c0 < 128; c0 += 16) {
            uint32_t rz[16], rr[16], rg[16], rh[16];
            LD_X16(rz, tmem + c0);
            LD_X16(rr, tmem + 128 + c0);
            LD_X16(rg, tmem + 256 + c0);
            LD_X16(rh, tmem + 384 + c0);
            TC_WAIT_LD();
            TC_FENCE_BEFORE();
            float o[16];
#pragma unroll
            for (int j = 0; j < 16; j++) {
                const int cc = c0 + j;
                float az = __uint_as_float(rz[j]) * TRUNC_DEBIAS;
                float ar = __uint_as_float(rr[j]) * TRUNC_DEBIAS;
                float ag = __uint_as_float(rg[j]) * TRUNC_DEBIAS;
                float ah = __uint_as_float(rh[j]) * TRUNC_DEBIAS;
                float z = 1.f / (1.f + __expf(-(az + bb[cc])));
                float r = 1.f / (1.f + __expf(-(ar + bb[128 + cc])));
                float g = tanhf(ag + bb[256 + cc] + r * (ah + bb[384 + cc]));
                o[j] = (1.f - z) * g + z * hrow[cc];
            }
#pragma unroll
            for (int q = 0; q < 4; q++)
                *reinterpret_cast<float4*>(orow + c0 + q * 4) =
                    make_float4(o[q * 4], o[q * 4 + 1], o[q * 4 + 2], o[q * 4 + 3]);
        }
    }

    __syncthreads();
    if (tid >= 256) {
        RELINQ_CG2();
        DEALLOC_CG2(tmem, 512);
    }
    CLUSTER_SYNC_();   // no CTA exits while peer's cg2 TMA/MMA may touch it
#endif // HAVE_TCGEN05
}

// ---------------------------------------------------------------------------
// Launch: 8 tensormaps (driver via dlopen), single kernel launch.
// ---------------------------------------------------------------------------
using TmapEncodeFn = CUresult (*)(
    CUtensorMap*, CUtensorMapDataType, cuuint32_t, void*,
    const cuuint64_t*, const cuuint64_t*, const cuuint32_t*, const cuuint32_t*,
    CUtensorMapInterleave, CUtensorMapSwizzle, CUtensorMapL2promotion,
    CUtensorMapFloatOOBfill);

static void make_map(TmapEncodeFn enc, CUtensorMap* m, const void* ptr,
                     uint64_t rows, uint32_t boxRows) {
    cuuint64_t dims[3]    = {(cuuint64_t)I_DIM, (cuuint64_t)rows, 1};
    cuuint64_t strides[2] = {(cuuint64_t)I_DIM * sizeof(float),
                             (cuuint64_t)rows * I_DIM * sizeof(float)};
    cuuint32_t box[3]     = {32u, boxRows, 1u};   // 32 f32 = 128B = SW128 atom
    cuuint32_t estr[3]    = {1u, 1u, 1u};
    enc(m, CU_TENSOR_MAP_DATA_TYPE_FLOAT32, 3, const_cast<void*>(ptr),
        dims, strides, box, estr,
        CU_TENSOR_MAP_INTERLEAVE_NONE, CU_TENSOR_MAP_SWIZZLE_128B,
        CU_TENSOR_MAP_L2_PROMOTION_L2_128B, CU_TENSOR_MAP_FLOAT_OOB_FILL_NONE);
}

extern "C" void kernel_launch(void* const* d_in, const int* in_sizes, int n_in,
                              void* d_out, int out_size)
{
    const float* x   = (const float*)d_in[0];
    const float* h   = (const float*)d_in[1];
    const float* Wiz = (const float*)d_in[2];
    const float* biz = (const float*)d_in[3];
    const float* Wir = (const float*)d_in[4];
    const float* bir = (const float*)d_in[5];
    const float* Wih = (const float*)d_in[6];
    const float* big = (const float*)d_in[7];
    const float* Whz = (const float*)d_in[8];
    const float* bhz = (const float*)d_in[9];
    const float* Whr = (const float*)d_in[10];
    const float* bhr = (const float*)d_in[11];
    const float* Whh = (const float*)d_in[12];
    const float* bhh = (const float*)d_in[13];
    float* out = (float*)d_out;

    static CUtensorMap mX, mH, mWiz, mWir, mWih, mWhz, mWhr, mWhh;
    {
        void* lib = dlopen("libcuda.so.1", RTLD_NOW | RTLD_GLOBAL);
        TmapEncodeFn enc = lib ? (TmapEncodeFn)dlsym(lib, "cuTensorMapEncodeTiled") : nullptr;
        if (enc) {
            make_map(enc, &mX,   x,   B_DIM, 128);
            make_map(enc, &mH,   h,   B_DIM, 128);
            make_map(enc, &mWiz, Wiz, H_DIM, 64);
            make_map(enc, &mWir, Wir, H_DIM, 64);
            make_map(enc, &mWih, Wih, H_DIM, 64);
            make_map(enc, &mWhz, Whz, H_DIM, 64);
            make_map(enc, &mWhr, Whr, H_DIM, 64);
            make_map(enc, &mWhh, Whh, H_DIM, 64);
        }
    }

    cudaFuncSetAttribute(gru_tc_kernel, cudaFuncAttributeMaxDynamicSharedMemorySize, SMEM_TOTAL_TC);
    dim3 grid(1024, 1);
    gru_tc_kernel<<<grid, 288, SMEM_TOTAL_TC>>>(
        mX, mH, mWiz, mWir, mWih, mWhz, mWhr, mWhh,
        h, biz, bir, big, bhz, bhr, bhh, out);
}